// round 1
// baseline (speedup 1.0000x reference)
#include <cuda_runtime.h>
#include <math.h>

#define BB 16
#define NN 1024
#define CC 768
#define HH 12
#define DH 64
#define EE 8
#define TT (BB*NN)

// ---------------- scratch (no allocations allowed) ----------------
__device__ float g_h1[(size_t)TT * CC];        // LN1 output
__device__ float g_qkv[(size_t)TT * 3 * CC];   // QKV
__device__ float g_o[(size_t)TT * CC];         // attention output
__device__ float g_h2[(size_t)TT * CC];        // LN2 output
__device__ int   g_cnt[EE];
__device__ int   g_list[EE * TT];
__device__ float g_wt[EE * TT];

// ---------------- LayerNorm (one block per token) ----------------
__global__ __launch_bounds__(256) void ln_kernel(const float* __restrict__ in,
    const float* __restrict__ gamma, const float* __restrict__ beta,
    float* __restrict__ out)
{
    int t = blockIdx.x;
    const float* row = in + (size_t)t * CC;
    float s = 0.f, s2 = 0.f;
    for (int i = threadIdx.x; i < CC; i += 256) { float v = row[i]; s += v; s2 += v * v; }
    __shared__ float sh[64];
    #pragma unroll
    for (int o = 16; o > 0; o >>= 1) { s += __shfl_xor_sync(~0u, s, o); s2 += __shfl_xor_sync(~0u, s2, o); }
    int w = threadIdx.x >> 5, l = threadIdx.x & 31;
    if (l == 0) { sh[w] = s; sh[32 + w] = s2; }
    __syncthreads();
    if (threadIdx.x == 0) {
        float a = 0.f, b = 0.f;
        #pragma unroll
        for (int i = 0; i < 8; i++) { a += sh[i]; b += sh[32 + i]; }
        sh[0] = a; sh[1] = b;
    }
    __syncthreads();
    float mean = sh[0] * (1.f / CC);
    float var  = sh[1] * (1.f / CC) - mean * mean;
    float rstd = rsqrtf(var + 1e-5f);
    float* orow = out + (size_t)t * CC;
    for (int i = threadIdx.x; i < CC; i += 256)
        orow[i] = (row[i] - mean) * rstd * gamma[i] + beta[i];
}

// ---------------- SGEMM 128x128x8, 256 threads, 8x8 micro-tile ----------------
// C = A(MxK) @ B(KxN)  [+ bias[col]] [+ resid(MxN)]
#define BM 128
#define BN 128
#define BKg 8

__global__ __launch_bounds__(256) void sgemm_kernel(
    const float* __restrict__ A, const float* __restrict__ Bm, float* __restrict__ Cm,
    int M, int Nn, int K,
    const float* __restrict__ bias, const float* __restrict__ resid)
{
    __shared__ float As[BKg][BM];
    __shared__ float Bs[BKg][BN];
    int bm = blockIdx.y * BM, bn = blockIdx.x * BN;
    int tid = threadIdx.x;
    int tx = tid & 15, ty = tid >> 4;
    int arow = tid >> 1, acol = (tid & 1) << 2;
    int brow = tid >> 5, bcol = (tid & 31) << 2;

    float acc[8][8];
    #pragma unroll
    for (int i = 0; i < 8; i++)
        #pragma unroll
        for (int j = 0; j < 8; j++) acc[i][j] = 0.f;

    const float* Ab = A + (size_t)(bm + arow) * K + acol;
    const float* Bb = Bm + (size_t)brow * Nn + bn + bcol;

    for (int k0 = 0; k0 < K; k0 += BKg) {
        float4 av = *(const float4*)(Ab + k0);
        As[acol + 0][arow] = av.x; As[acol + 1][arow] = av.y;
        As[acol + 2][arow] = av.z; As[acol + 3][arow] = av.w;
        *(float4*)&Bs[brow][bcol] = *(const float4*)(Bb + (size_t)k0 * Nn);
        __syncthreads();
        #pragma unroll
        for (int kk = 0; kk < BKg; kk++) {
            float ra[8], rb[8];
            *(float4*)(ra)     = *(float4*)&As[kk][ty * 8];
            *(float4*)(ra + 4) = *(float4*)&As[kk][ty * 8 + 4];
            *(float4*)(rb)     = *(float4*)&Bs[kk][tx * 8];
            *(float4*)(rb + 4) = *(float4*)&Bs[kk][tx * 8 + 4];
            #pragma unroll
            for (int i = 0; i < 8; i++)
                #pragma unroll
                for (int j = 0; j < 8; j++) acc[i][j] += ra[i] * rb[j];
        }
        __syncthreads();
    }

    #pragma unroll
    for (int i = 0; i < 8; i++) {
        int row = bm + ty * 8 + i;
        float* cp = Cm + (size_t)row * Nn + bn + tx * 8;
        const float* rp = resid ? (resid + (size_t)row * Nn + bn + tx * 8) : nullptr;
        #pragma unroll
        for (int j = 0; j < 8; j += 4) {
            float4 v = make_float4(acc[i][j], acc[i][j+1], acc[i][j+2], acc[i][j+3]);
            if (bias) {
                const float* bp = bias + bn + tx * 8 + j;
                v.x += bp[0]; v.y += bp[1]; v.z += bp[2]; v.w += bp[3];
            }
            if (rp) {
                float4 r = *(const float4*)(rp + j);
                v.x += r.x; v.y += r.y; v.z += r.z; v.w += r.w;
            }
            *(float4*)(cp + j) = v;
        }
    }
}

// ---------------- fp32 flash attention ----------------
// grid (N/64, B*H); block 256; dynamic smem: 4 tiles of 64 x 68 floats
#define APAD 68
#define ATTN_SMEM (4 * 64 * APAD * sizeof(float))

__global__ __launch_bounds__(256) void attn_kernel(const float* __restrict__ qkv,
                                                   float* __restrict__ o)
{
    extern __shared__ float smem[];
    float* Qs = smem;
    float* Ks = Qs + 64 * APAD;
    float* Vs = Ks + 64 * APAD;
    float* Ps = Vs + 64 * APAD;

    int bh = blockIdx.y;
    int bb = bh / HH, hh = bh % HH;
    int q0 = blockIdx.x * 64;
    int tid = threadIdx.x;
    int tx = tid & 15, ty = tid >> 4;
    const float scale = 0.125f;   // 64^-0.5

    // load Q (scaled): 64x64 floats -> 1024 float4s -> 4 per thread
    #pragma unroll
    for (int it = 0; it < 4; it++) {
        int idx = tid + it * 256;
        int r = idx >> 4, c4 = (idx & 15) << 2;
        size_t t = (size_t)(bb * NN + q0 + r);
        float4 v = *(const float4*)&qkv[((t * 3 + 0) * HH + hh) * DH + c4];
        v.x *= scale; v.y *= scale; v.z *= scale; v.w *= scale;
        *(float4*)&Qs[r * APAD + c4] = v;
    }

    float m_i[4], l_i[4], accO[4][4];
    #pragma unroll
    for (int i = 0; i < 4; i++) {
        m_i[i] = -1e30f; l_i[i] = 0.f;
        #pragma unroll
        for (int j = 0; j < 4; j++) accO[i][j] = 0.f;
    }

    for (int kc = 0; kc < NN; kc += 64) {
        __syncthreads();   // Q ready (first iter); previous consumers of Ks/Vs/Ps done
        #pragma unroll
        for (int it = 0; it < 4; it++) {
            int idx = tid + it * 256;
            int r = idx >> 4, c4 = (idx & 15) << 2;
            size_t t = (size_t)(bb * NN + kc + r);
            *(float4*)&Ks[r * APAD + c4] = *(const float4*)&qkv[((t * 3 + 1) * HH + hh) * DH + c4];
            *(float4*)&Vs[r * APAD + c4] = *(const float4*)&qkv[((t * 3 + 2) * HH + hh) * DH + c4];
        }
        __syncthreads();

        // S = Q K^T (4x4 per thread)
        float s[4][4];
        #pragma unroll
        for (int i = 0; i < 4; i++)
            #pragma unroll
            for (int j = 0; j < 4; j++) s[i][j] = 0.f;
        for (int d = 0; d < 64; d += 4) {
            float4 qv[4], kv[4];
            #pragma unroll
            for (int i = 0; i < 4; i++) qv[i] = *(float4*)&Qs[(ty * 4 + i) * APAD + d];
            #pragma unroll
            for (int j = 0; j < 4; j++) kv[j] = *(float4*)&Ks[(tx * 4 + j) * APAD + d];
            #pragma unroll
            for (int i = 0; i < 4; i++)
                #pragma unroll
                for (int j = 0; j < 4; j++)
                    s[i][j] += qv[i].x * kv[j].x + qv[i].y * kv[j].y
                             + qv[i].z * kv[j].z + qv[i].w * kv[j].w;
        }

        // online softmax across the 16-thread row group
        #pragma unroll
        for (int i = 0; i < 4; i++) {
            float mx = fmaxf(fmaxf(s[i][0], s[i][1]), fmaxf(s[i][2], s[i][3]));
            #pragma unroll
            for (int off = 1; off < 16; off <<= 1)
                mx = fmaxf(mx, __shfl_xor_sync(~0u, mx, off, 16));
            float mnew = fmaxf(m_i[i], mx);
            float alpha = __expf(m_i[i] - mnew);
            float p0 = __expf(s[i][0] - mnew), p1 = __expf(s[i][1] - mnew);
            float p2 = __expf(s[i][2] - mnew), p3 = __expf(s[i][3] - mnew);
            float rs = p0 + p1 + p2 + p3;
            #pragma unroll
            for (int off = 1; off < 16; off <<= 1)
                rs += __shfl_xor_sync(~0u, rs, off, 16);
            l_i[i] = l_i[i] * alpha + rs;
            m_i[i] = mnew;
            #pragma unroll
            for (int j = 0; j < 4; j++) accO[i][j] *= alpha;
            *(float4*)&Ps[(ty * 4 + i) * APAD + tx * 4] = make_float4(p0, p1, p2, p3);
        }
        __syncthreads();

        // O += P @ V
        for (int kk = 0; kk < 64; kk += 4) {
            float4 pv[4];
            #pragma unroll
            for (int i = 0; i < 4; i++) pv[i] = *(float4*)&Ps[(ty * 4 + i) * APAD + kk];
            #pragma unroll
            for (int l = 0; l < 4; l++) {
                float4 vr = *(float4*)&Vs[(kk + l) * APAD + tx * 4];
                #pragma unroll
                for (int i = 0; i < 4; i++) {
                    float c = (l == 0) ? pv[i].x : (l == 1) ? pv[i].y : (l == 2) ? pv[i].z : pv[i].w;
                    accO[i][0] += c * vr.x; accO[i][1] += c * vr.y;
                    accO[i][2] += c * vr.z; accO[i][3] += c * vr.w;
                }
            }
        }
    }

    #pragma unroll
    for (int i = 0; i < 4; i++) {
        float inv = 1.f / l_i[i];
        size_t t = (size_t)(bb * NN + q0 + ty * 4 + i);
        *(float4*)&o[t * CC + hh * DH + tx * 4] =
            make_float4(accO[i][0] * inv, accO[i][1] * inv, accO[i][2] * inv, accO[i][3] * inv);
    }
}

// ---------------- router: logits -> LN -> softmax -> +noise -> top2 ----------------
__global__ __launch_bounds__(256) void route_kernel(
    const float* __restrict__ h2, const float* __restrict__ route_w,
    const float* __restrict__ route_b, const float* __restrict__ rln_g,
    const float* __restrict__ rln_b, const float* __restrict__ noise)
{
    int warp = threadIdx.x >> 5, lane = threadIdx.x & 31;
    int t = blockIdx.x * 8 + warp;
    const float* hrow = h2 + (size_t)t * CC;
    float acc[EE];
    #pragma unroll
    for (int e = 0; e < EE; e++) acc[e] = 0.f;
    for (int c = lane; c < CC; c += 32) {
        float hv = hrow[c];
        const float* rw = route_w + (size_t)c * EE;
        #pragma unroll
        for (int e = 0; e < EE; e++) acc[e] += hv * rw[e];
    }
    #pragma unroll
    for (int e = 0; e < EE; e++)
        #pragma unroll
        for (int off = 16; off > 0; off >>= 1)
            acc[e] += __shfl_xor_sync(~0u, acc[e], off);

    if (lane == 0) {
        float lg[EE];
        float mean = 0.f;
        #pragma unroll
        for (int e = 0; e < EE; e++) { lg[e] = acc[e] + route_b[e]; mean += lg[e]; }
        mean *= (1.f / EE);
        float var = 0.f;
        #pragma unroll
        for (int e = 0; e < EE; e++) { float d = lg[e] - mean; var += d * d; }
        var *= (1.f / EE);
        float rstd = rsqrtf(var + 1e-5f);
        float mx = -1e30f;
        #pragma unroll
        for (int e = 0; e < EE; e++) { lg[e] = (lg[e] - mean) * rstd * rln_g[e] + rln_b[e]; mx = fmaxf(mx, lg[e]); }
        float den = 0.f;
        float r[EE];
        #pragma unroll
        for (int e = 0; e < EE; e++) { r[e] = __expf(lg[e] - mx); den += r[e]; }
        float inv = 1.f / den;
        const float* nrow = noise + (size_t)t * EE;
        #pragma unroll
        for (int e = 0; e < EE; e++) r[e] = r[e] * inv + nrow[e] * 0.125f;

        int i1 = 0;
        #pragma unroll
        for (int e = 1; e < EE; e++) if (r[e] > r[i1]) i1 = e;
        int i2 = (i1 == 0) ? 1 : 0;
        #pragma unroll
        for (int e = 0; e < EE; e++) if (e != i1 && r[e] > r[i2]) i2 = e;

        float vm = fmaxf(r[i1], r[i2]);
        float e1 = __expf(r[i1] - vm), e2 = __expf(r[i2] - vm);
        float wsum = 1.f / (e1 + e2);
        float w1 = e1 * wsum, w2 = e2 * wsum;

        int p1 = atomicAdd(&g_cnt[i1], 1);
        g_list[i1 * TT + p1] = t; g_wt[i1 * TT + p1] = w1;
        int p2 = atomicAdd(&g_cnt[i2], 1);
        g_list[i2 * TT + p2] = t; g_wt[i2 * TT + p2] = w2;
    }
}

__global__ void zero_cnt_kernel() { if (threadIdx.x < EE) g_cnt[threadIdx.x] = 0; }

// ---------------- grouped MoE gather-GEMM ----------------
// grid (CC/BN, TT/BM, EE); out[token] += w * (h2[token] @ expert_w[e] + expert_b[e])
__global__ __launch_bounds__(256) void moe_gemm_kernel(
    const float* __restrict__ h2, const float* __restrict__ ew,
    const float* __restrict__ eb, float* __restrict__ out)
{
    int e = blockIdx.z;
    int cnt = g_cnt[e];
    int bm = blockIdx.y * BM;
    if (bm >= cnt) return;
    int bn = blockIdx.x * BN;

    __shared__ float As[BKg][BM];
    __shared__ float Bs[BKg][BN];
    __shared__ int   stok[BM];
    __shared__ float swt[BM];

    int tid = threadIdx.x;
    if (tid < BM) {
        int m = bm + tid;
        if (m < cnt) { stok[tid] = g_list[e * TT + m]; swt[tid] = g_wt[e * TT + m]; }
        else         { stok[tid] = -1; swt[tid] = 0.f; }
    }
    __syncthreads();

    int tx = tid & 15, ty = tid >> 4;
    int arow = tid >> 1, acol = (tid & 1) << 2;
    int brow = tid >> 5, bcol = (tid & 31) << 2;

    float acc[8][8];
    #pragma unroll
    for (int i = 0; i < 8; i++)
        #pragma unroll
        for (int j = 0; j < 8; j++) acc[i][j] = 0.f;

    int tokA = stok[arow];
    const float* Arow = (tokA >= 0) ? (h2 + (size_t)tokA * CC + acol) : nullptr;
    const float* Bb = ew + ((size_t)e * CC + brow) * CC + bn + bcol;

    for (int k0 = 0; k0 < CC; k0 += BKg) {
        float4 av = Arow ? *(const float4*)(Arow + k0) : make_float4(0.f, 0.f, 0.f, 0.f);
        As[acol + 0][arow] = av.x; As[acol + 1][arow] = av.y;
        As[acol + 2][arow] = av.z; As[acol + 3][arow] = av.w;
        *(float4*)&Bs[brow][bcol] = *(const float4*)(Bb + (size_t)k0 * CC);
        __syncthreads();
        #pragma unroll
        for (int kk = 0; kk < BKg; kk++) {
            float ra[8], rb[8];
            *(float4*)(ra)     = *(float4*)&As[kk][ty * 8];
            *(float4*)(ra + 4) = *(float4*)&As[kk][ty * 8 + 4];
            *(float4*)(rb)     = *(float4*)&Bs[kk][tx * 8];
            *(float4*)(rb + 4) = *(float4*)&Bs[kk][tx * 8 + 4];
            #pragma unroll
            for (int i = 0; i < 8; i++)
                #pragma unroll
                for (int j = 0; j < 8; j++) acc[i][j] += ra[i] * rb[j];
        }
        __syncthreads();
    }

    #pragma unroll
    for (int i = 0; i < 8; i++) {
        int tk = stok[ty * 8 + i];
        if (tk < 0) continue;
        float w = swt[ty * 8 + i];
        float* op = out + (size_t)tk * CC + bn + tx * 8;
        const float* bp = eb + (size_t)e * CC + bn + tx * 8;
        #pragma unroll
        for (int j = 0; j < 8; j++)
            atomicAdd(op + j, w * (acc[i][j] + bp[j]));
    }
}

// ---------------- launch ----------------
extern "C" void kernel_launch(void* const* d_in, const int* in_sizes, int n_in,
                              void* d_out, int out_size)
{
    const float* x       = (const float*)d_in[0];
    const float* noise   = (const float*)d_in[1];
    const float* ln1_g   = (const float*)d_in[2];
    const float* ln1_b   = (const float*)d_in[3];
    const float* qkv_w   = (const float*)d_in[4];
    const float* proj_w  = (const float*)d_in[5];
    const float* proj_b  = (const float*)d_in[6];
    const float* ln2_g   = (const float*)d_in[7];
    const float* ln2_b   = (const float*)d_in[8];
    const float* route_w = (const float*)d_in[9];
    const float* route_b = (const float*)d_in[10];
    const float* rln_g   = (const float*)d_in[11];
    const float* rln_b   = (const float*)d_in[12];
    const float* exp_w   = (const float*)d_in[13];
    const float* exp_b   = (const float*)d_in[14];
    float* out = (float*)d_out;

    float *h1, *qkv, *o, *h2;
    cudaGetSymbolAddress((void**)&h1,  g_h1);
    cudaGetSymbolAddress((void**)&qkv, g_qkv);
    cudaGetSymbolAddress((void**)&o,   g_o);
    cudaGetSymbolAddress((void**)&h2,  g_h2);

    cudaFuncSetAttribute(attn_kernel, cudaFuncAttributeMaxDynamicSharedMemorySize, (int)ATTN_SMEM);

    // 1) LN1
    ln_kernel<<<TT, 256>>>(x, ln1_g, ln1_b, h1);
    // 2) QKV GEMM: [T,768] @ [768,2304]
    sgemm_kernel<<<dim3(3 * CC / BN, TT / BM), 256>>>(h1, qkv_w, qkv, TT, 3 * CC, CC, nullptr, nullptr);
    // 3) attention
    attn_kernel<<<dim3(NN / 64, BB * HH), 256, ATTN_SMEM>>>(qkv, o);
    // 4) proj + bias + residual -> d_out (= x1)
    sgemm_kernel<<<dim3(CC / BN, TT / BM), 256>>>(o, proj_w, out, TT, CC, CC, proj_b, x);
    // 5) LN2
    ln_kernel<<<TT, 256>>>(out, ln2_g, ln2_b, h2);
    // 6) routing
    zero_cnt_kernel<<<1, 32>>>();
    route_kernel<<<TT / 8, 256>>>(h2, route_w, route_b, rln_g, rln_b, noise);
    // 7) MoE grouped GEMM, accumulates into d_out
    moe_gemm_kernel<<<dim3(CC / BN, TT / BM, EE), 256>>>(h2, exp_w, exp_b, out);
}

// round 2
// speedup vs baseline: 1.3952x; 1.3952x over previous
#include <cuda_runtime.h>
#include <math.h>

#define BB 16
#define NN 1024
#define CC 768
#define HH 12
#define DH 64
#define EE 8
#define TT (BB*NN)

// ---------------- scratch (no allocations allowed) ----------------
__device__ float g_h1[(size_t)TT * CC];        // LN1 output
__device__ float g_qkv[(size_t)TT * 3 * CC];   // QKV
__device__ float g_o[(size_t)TT * CC];         // attention output
__device__ float g_h2[(size_t)TT * CC];        // LN2 output
__device__ int   g_cnt[EE];
__device__ int   g_list[EE * TT];
__device__ float g_wt[EE * TT];

// ---------------- LayerNorm (one block per token) ----------------
__global__ __launch_bounds__(256) void ln_kernel(const float* __restrict__ in,
    const float* __restrict__ gamma, const float* __restrict__ beta,
    float* __restrict__ out)
{
    int t = blockIdx.x;
    const float* row = in + (size_t)t * CC;
    float s = 0.f, s2 = 0.f;
    for (int i = threadIdx.x; i < CC; i += 256) { float v = row[i]; s += v; s2 += v * v; }
    __shared__ float sh[64];
    #pragma unroll
    for (int o = 16; o > 0; o >>= 1) { s += __shfl_xor_sync(~0u, s, o); s2 += __shfl_xor_sync(~0u, s2, o); }
    int w = threadIdx.x >> 5, l = threadIdx.x & 31;
    if (l == 0) { sh[w] = s; sh[32 + w] = s2; }
    __syncthreads();
    if (threadIdx.x == 0) {
        float a = 0.f, b = 0.f;
        #pragma unroll
        for (int i = 0; i < 8; i++) { a += sh[i]; b += sh[32 + i]; }
        sh[0] = a; sh[1] = b;
    }
    __syncthreads();
    float mean = sh[0] * (1.f / CC);
    float var  = sh[1] * (1.f / CC) - mean * mean;
    float rstd = rsqrtf(var + 1e-5f);
    float* orow = out + (size_t)t * CC;
    for (int i = threadIdx.x; i < CC; i += 256)
        orow[i] = (row[i] - mean) * rstd * gamma[i] + beta[i];
}

// ---------------- TF32 tensor-core GEMM 128x128x16 ----------------
#define BM 128
#define BN 128
#define BK 16
#define ASTR (BM + 8)   // stride % 32 == 8 -> conflict-free frag reads
#define BSTR (BN + 8)

__device__ __forceinline__ unsigned f2tf(float f) {
    unsigned u; asm("cvt.rna.tf32.f32 %0, %1;" : "=r"(u) : "f"(f)); return u;
}

__device__ __forceinline__ void mma8(float* c, const unsigned* a, const unsigned* b) {
    asm volatile("mma.sync.aligned.m16n8k8.row.col.f32.tf32.tf32.f32 "
        "{%0,%1,%2,%3}, {%4,%5,%6,%7}, {%8,%9}, {%0,%1,%2,%3};"
        : "+f"(c[0]), "+f"(c[1]), "+f"(c[2]), "+f"(c[3])
        : "r"(a[0]), "r"(a[1]), "r"(a[2]), "r"(a[3]), "r"(b[0]), "r"(b[1]));
}

// C = A(MxK) @ B(KxN) [+bias] [+resid]    (MOE: gathered rows, weighted atomic scatter)
template<bool MOE>
__global__ __launch_bounds__(256) void tf32_gemm_kernel(
    const float* __restrict__ A, const float* __restrict__ Bm, float* __restrict__ Cm,
    int Nn, int K,
    const float* __restrict__ bias, const float* __restrict__ resid)
{
    __shared__ unsigned As[2][BK][ASTR];
    __shared__ unsigned Bs[2][BK][BSTR];
    __shared__ int   stok[BM];
    __shared__ float swt[BM];

    int bm = blockIdx.y * BM, bn = blockIdx.x * BN;
    int tid = threadIdx.x;
    int e = 0, cnt = 0;
    if (MOE) {
        e = blockIdx.z;
        cnt = g_cnt[e];
        if (bm >= cnt) return;
        if (tid < BM) {
            int m = bm + tid;
            if (m < cnt) { stok[tid] = g_list[e * TT + m]; swt[tid] = g_wt[e * TT + m]; }
            else         { stok[tid] = -1; swt[tid] = 0.f; }
        }
        __syncthreads();
    }

    // A fill mapping: row = tid&127, kcols [ (tid>>7)*8, +8 )  -> conflict-free smem stores
    int lrowA = tid & 127;
    int kcolA = (tid >> 7) * 8;
    const float* Aptr;
    if (MOE) {
        int tok = stok[lrowA];
        Aptr = (tok >= 0) ? A + (size_t)tok * K + kcolA : nullptr;
    } else {
        Aptr = A + (size_t)(bm + lrowA) * K + kcolA;
    }
    // B fill mapping: rows {tid>>5, +8}, cols (tid&31)*4
    int rowB = tid >> 5;
    int colB = (tid & 31) << 2;
    const float* Bbase = MOE ? (Bm + (size_t)e * K * Nn) : Bm;
    const float* Bptr = Bbase + (size_t)rowB * Nn + bn + colB;

    float4 pa0, pa1, pb0, pb1;
    const float4 z4 = make_float4(0.f, 0.f, 0.f, 0.f);

    // prefetch stage 0
    pa0 = Aptr ? *(const float4*)(Aptr + 0) : z4;
    pa1 = Aptr ? *(const float4*)(Aptr + 4) : z4;
    pb0 = *(const float4*)(Bptr);
    pb1 = *(const float4*)(Bptr + (size_t)8 * Nn);

    // store stage 0
    {
        As[0][kcolA + 0][lrowA] = f2tf(pa0.x); As[0][kcolA + 1][lrowA] = f2tf(pa0.y);
        As[0][kcolA + 2][lrowA] = f2tf(pa0.z); As[0][kcolA + 3][lrowA] = f2tf(pa0.w);
        As[0][kcolA + 4][lrowA] = f2tf(pa1.x); As[0][kcolA + 5][lrowA] = f2tf(pa1.y);
        As[0][kcolA + 6][lrowA] = f2tf(pa1.z); As[0][kcolA + 7][lrowA] = f2tf(pa1.w);
        uint4 u0 = make_uint4(f2tf(pb0.x), f2tf(pb0.y), f2tf(pb0.z), f2tf(pb0.w));
        uint4 u1 = make_uint4(f2tf(pb1.x), f2tf(pb1.y), f2tf(pb1.z), f2tf(pb1.w));
        *(uint4*)&Bs[0][rowB][colB] = u0;
        *(uint4*)&Bs[0][rowB + 8][colB] = u1;
    }
    __syncthreads();

    int lane = tid & 31, wid = tid >> 5;
    int wm = (wid & 3) * 32;     // 4 warps along M
    int wn = (wid >> 2) * 64;    // 2 warps along N
    int g = lane >> 2, c = lane & 3;

    float acc[2][8][4];
    #pragma unroll
    for (int mi = 0; mi < 2; mi++)
        #pragma unroll
        for (int ni = 0; ni < 8; ni++)
            #pragma unroll
            for (int q = 0; q < 4; q++) acc[mi][ni][q] = 0.f;

    int nIter = K / BK;
    for (int it = 0; it < nIter; it++) {
        int cur = it & 1, nxt = cur ^ 1;
        int k0n = (it + 1) * BK;
        if (it + 1 < nIter) {
            pa0 = Aptr ? *(const float4*)(Aptr + k0n) : z4;
            pa1 = Aptr ? *(const float4*)(Aptr + k0n + 4) : z4;
            pb0 = *(const float4*)(Bptr + (size_t)k0n * Nn);
            pb1 = *(const float4*)(Bptr + (size_t)(k0n + 8) * Nn);
        }

        #pragma unroll
        for (int kk = 0; kk < BK; kk += 8) {
            unsigned af[2][4], bf[8][2];
            #pragma unroll
            for (int mi = 0; mi < 2; mi++) {
                af[mi][0] = As[cur][kk + c][wm + mi * 16 + g];
                af[mi][1] = As[cur][kk + c][wm + mi * 16 + g + 8];
                af[mi][2] = As[cur][kk + c + 4][wm + mi * 16 + g];
                af[mi][3] = As[cur][kk + c + 4][wm + mi * 16 + g + 8];
            }
            #pragma unroll
            for (int ni = 0; ni < 8; ni++) {
                bf[ni][0] = Bs[cur][kk + c][wn + ni * 8 + g];
                bf[ni][1] = Bs[cur][kk + c + 4][wn + ni * 8 + g];
            }
            #pragma unroll
            for (int mi = 0; mi < 2; mi++)
                #pragma unroll
                for (int ni = 0; ni < 8; ni++)
                    mma8(acc[mi][ni], af[mi], bf[ni]);
        }

        if (it + 1 < nIter) {
            As[nxt][kcolA + 0][lrowA] = f2tf(pa0.x); As[nxt][kcolA + 1][lrowA] = f2tf(pa0.y);
            As[nxt][kcolA + 2][lrowA] = f2tf(pa0.z); As[nxt][kcolA + 3][lrowA] = f2tf(pa0.w);
            As[nxt][kcolA + 4][lrowA] = f2tf(pa1.x); As[nxt][kcolA + 5][lrowA] = f2tf(pa1.y);
            As[nxt][kcolA + 6][lrowA] = f2tf(pa1.z); As[nxt][kcolA + 7][lrowA] = f2tf(pa1.w);
            uint4 u0 = make_uint4(f2tf(pb0.x), f2tf(pb0.y), f2tf(pb0.z), f2tf(pb0.w));
            uint4 u1 = make_uint4(f2tf(pb1.x), f2tf(pb1.y), f2tf(pb1.z), f2tf(pb1.w));
            *(uint4*)&Bs[nxt][rowB][colB] = u0;
            *(uint4*)&Bs[nxt][rowB + 8][colB] = u1;
        }
        __syncthreads();
    }

    // epilogue
    #pragma unroll
    for (int mi = 0; mi < 2; mi++) {
        int rl0 = wm + mi * 16 + g;
        int rl1 = rl0 + 8;
        if (MOE) {
            int tk0 = stok[rl0], tk1 = stok[rl1];
            float w0 = swt[rl0], w1 = swt[rl1];
            #pragma unroll
            for (int ni = 0; ni < 8; ni++) {
                int cn = bn + wn + ni * 8 + 2 * c;
                float b0 = bias[(size_t)e * Nn + cn], b1 = bias[(size_t)e * Nn + cn + 1];
                if (tk0 >= 0) {
                    float* p = Cm + (size_t)tk0 * Nn + cn;
                    atomicAdd(p,     w0 * (acc[mi][ni][0] + b0));
                    atomicAdd(p + 1, w0 * (acc[mi][ni][1] + b1));
                }
                if (tk1 >= 0) {
                    float* p = Cm + (size_t)tk1 * Nn + cn;
                    atomicAdd(p,     w1 * (acc[mi][ni][2] + b0));
                    atomicAdd(p + 1, w1 * (acc[mi][ni][3] + b1));
                }
            }
        } else {
            int r0 = bm + rl0, r1 = bm + rl1;
            #pragma unroll
            for (int ni = 0; ni < 8; ni++) {
                int cn = bn + wn + ni * 8 + 2 * c;
                float2 v0 = make_float2(acc[mi][ni][0], acc[mi][ni][1]);
                float2 v1 = make_float2(acc[mi][ni][2], acc[mi][ni][3]);
                if (bias) {
                    float b0 = bias[cn], b1 = bias[cn + 1];
                    v0.x += b0; v0.y += b1; v1.x += b0; v1.y += b1;
                }
                if (resid) {
                    float2 r0v = *(const float2*)(resid + (size_t)r0 * Nn + cn);
                    float2 r1v = *(const float2*)(resid + (size_t)r1 * Nn + cn);
                    v0.x += r0v.x; v0.y += r0v.y; v1.x += r1v.x; v1.y += r1v.y;
                }
                *(float2*)(Cm + (size_t)r0 * Nn + cn) = v0;
                *(float2*)(Cm + (size_t)r1 * Nn + cn) = v1;
            }
        }
    }
}

// ---------------- fp32 flash attention (unchanged this round) ----------------
#define APAD 68
#define ATTN_SMEM (4 * 64 * APAD * sizeof(float))

__global__ __launch_bounds__(256) void attn_kernel(const float* __restrict__ qkv,
                                                   float* __restrict__ o)
{
    extern __shared__ float smem[];
    float* Qs = smem;
    float* Ks = Qs + 64 * APAD;
    float* Vs = Ks + 64 * APAD;
    float* Ps = Vs + 64 * APAD;

    int bh = blockIdx.y;
    int bb = bh / HH, hh = bh % HH;
    int q0 = blockIdx.x * 64;
    int tid = threadIdx.x;
    int tx = tid & 15, ty = tid >> 4;
    const float scale = 0.125f;

    #pragma unroll
    for (int it = 0; it < 4; it++) {
        int idx = tid + it * 256;
        int r = idx >> 4, c4 = (idx & 15) << 2;
        size_t t = (size_t)(bb * NN + q0 + r);
        float4 v = *(const float4*)&qkv[((t * 3 + 0) * HH + hh) * DH + c4];
        v.x *= scale; v.y *= scale; v.z *= scale; v.w *= scale;
        *(float4*)&Qs[r * APAD + c4] = v;
    }

    float m_i[4], l_i[4], accO[4][4];
    #pragma unroll
    for (int i = 0; i < 4; i++) {
        m_i[i] = -1e30f; l_i[i] = 0.f;
        #pragma unroll
        for (int j = 0; j < 4; j++) accO[i][j] = 0.f;
    }

    for (int kc = 0; kc < NN; kc += 64) {
        __syncthreads();
        #pragma unroll
        for (int it = 0; it < 4; it++) {
            int idx = tid + it * 256;
            int r = idx >> 4, c4 = (idx & 15) << 2;
            size_t t = (size_t)(bb * NN + kc + r);
            *(float4*)&Ks[r * APAD + c4] = *(const float4*)&qkv[((t * 3 + 1) * HH + hh) * DH + c4];
            *(float4*)&Vs[r * APAD + c4] = *(const float4*)&qkv[((t * 3 + 2) * HH + hh) * DH + c4];
        }
        __syncthreads();

        float s[4][4];
        #pragma unroll
        for (int i = 0; i < 4; i++)
            #pragma unroll
            for (int j = 0; j < 4; j++) s[i][j] = 0.f;
        for (int d = 0; d < 64; d += 4) {
            float4 qv[4], kv[4];
            #pragma unroll
            for (int i = 0; i < 4; i++) qv[i] = *(float4*)&Qs[(ty * 4 + i) * APAD + d];
            #pragma unroll
            for (int j = 0; j < 4; j++) kv[j] = *(float4*)&Ks[(tx * 4 + j) * APAD + d];
            #pragma unroll
            for (int i = 0; i < 4; i++)
                #pragma unroll
                for (int j = 0; j < 4; j++)
                    s[i][j] += qv[i].x * kv[j].x + qv[i].y * kv[j].y
                             + qv[i].z * kv[j].z + qv[i].w * kv[j].w;
        }

        #pragma unroll
        for (int i = 0; i < 4; i++) {
            float mx = fmaxf(fmaxf(s[i][0], s[i][1]), fmaxf(s[i][2], s[i][3]));
            #pragma unroll
            for (int off = 1; off < 16; off <<= 1)
                mx = fmaxf(mx, __shfl_xor_sync(~0u, mx, off, 16));
            float mnew = fmaxf(m_i[i], mx);
            float alpha = __expf(m_i[i] - mnew);
            float p0 = __expf(s[i][0] - mnew), p1 = __expf(s[i][1] - mnew);
            float p2 = __expf(s[i][2] - mnew), p3 = __expf(s[i][3] - mnew);
            float rs = p0 + p1 + p2 + p3;
            #pragma unroll
            for (int off = 1; off < 16; off <<= 1)
                rs += __shfl_xor_sync(~0u, rs, off, 16);
            l_i[i] = l_i[i] * alpha + rs;
            m_i[i] = mnew;
            #pragma unroll
            for (int j = 0; j < 4; j++) accO[i][j] *= alpha;
            *(float4*)&Ps[(ty * 4 + i) * APAD + tx * 4] = make_float4(p0, p1, p2, p3);
        }
        __syncthreads();

        for (int kk = 0; kk < 64; kk += 4) {
            float4 pv[4];
            #pragma unroll
            for (int i = 0; i < 4; i++) pv[i] = *(float4*)&Ps[(ty * 4 + i) * APAD + kk];
            #pragma unroll
            for (int l = 0; l < 4; l++) {
                float4 vr = *(float4*)&Vs[(kk + l) * APAD + tx * 4];
                #pragma unroll
                for (int i = 0; i < 4; i++) {
                    float cc = (l == 0) ? pv[i].x : (l == 1) ? pv[i].y : (l == 2) ? pv[i].z : pv[i].w;
                    accO[i][0] += cc * vr.x; accO[i][1] += cc * vr.y;
                    accO[i][2] += cc * vr.z; accO[i][3] += cc * vr.w;
                }
            }
        }
    }

    #pragma unroll
    for (int i = 0; i < 4; i++) {
        float inv = 1.f / l_i[i];
        size_t t = (size_t)(bb * NN + q0 + ty * 4 + i);
        *(float4*)&o[t * CC + hh * DH + tx * 4] =
            make_float4(accO[i][0] * inv, accO[i][1] * inv, accO[i][2] * inv, accO[i][3] * inv);
    }
}

// ---------------- router ----------------
__global__ __launch_bounds__(256) void route_kernel(
    const float* __restrict__ h2, const float* __restrict__ route_w,
    const float* __restrict__ route_b, const float* __restrict__ rln_g,
    const float* __restrict__ rln_b, const float* __restrict__ noise)
{
    int warp = threadIdx.x >> 5, lane = threadIdx.x & 31;
    int t = blockIdx.x * 8 + warp;
    const float* hrow = h2 + (size_t)t * CC;
    float acc[EE];
    #pragma unroll
    for (int e = 0; e < EE; e++) acc[e] = 0.f;
    for (int c = lane; c < CC; c += 32) {
        float hv = hrow[c];
        const float* rw = route_w + (size_t)c * EE;
        #pragma unroll
        for (int e = 0; e < EE; e++) acc[e] += hv * rw[e];
    }
    #pragma unroll
    for (int e = 0; e < EE; e++)
        #pragma unroll
        for (int off = 16; off > 0; off >>= 1)
            acc[e] += __shfl_xor_sync(~0u, acc[e], off);

    if (lane == 0) {
        float lg[EE];
        float mean = 0.f;
        #pragma unroll
        for (int e = 0; e < EE; e++) { lg[e] = acc[e] + route_b[e]; mean += lg[e]; }
        mean *= (1.f / EE);
        float var = 0.f;
        #pragma unroll
        for (int e = 0; e < EE; e++) { float d = lg[e] - mean; var += d * d; }
        var *= (1.f / EE);
        float rstd = rsqrtf(var + 1e-5f);
        float mx = -1e30f;
        #pragma unroll
        for (int e = 0; e < EE; e++) { lg[e] = (lg[e] - mean) * rstd * rln_g[e] + rln_b[e]; mx = fmaxf(mx, lg[e]); }
        float den = 0.f;
        float r[EE];
        #pragma unroll
        for (int e = 0; e < EE; e++) { r[e] = __expf(lg[e] - mx); den += r[e]; }
        float inv = 1.f / den;
        const float* nrow = noise + (size_t)t * EE;
        #pragma unroll
        for (int e = 0; e < EE; e++) r[e] = r[e] * inv + nrow[e] * 0.125f;

        int i1 = 0;
        #pragma unroll
        for (int e = 1; e < EE; e++) if (r[e] > r[i1]) i1 = e;
        int i2 = (i1 == 0) ? 1 : 0;
        #pragma unroll
        for (int e = 0; e < EE; e++) if (e != i1 && r[e] > r[i2]) i2 = e;

        float vm = fmaxf(r[i1], r[i2]);
        float e1 = __expf(r[i1] - vm), e2 = __expf(r[i2] - vm);
        float wsum = 1.f / (e1 + e2);
        float w1 = e1 * wsum, w2 = e2 * wsum;

        int p1 = atomicAdd(&g_cnt[i1], 1);
        g_list[i1 * TT + p1] = t; g_wt[i1 * TT + p1] = w1;
        int p2 = atomicAdd(&g_cnt[i2], 1);
        g_list[i2 * TT + p2] = t; g_wt[i2 * TT + p2] = w2;
    }
}

__global__ void zero_cnt_kernel() { if (threadIdx.x < EE) g_cnt[threadIdx.x] = 0; }

// ---------------- launch ----------------
extern "C" void kernel_launch(void* const* d_in, const int* in_sizes, int n_in,
                              void* d_out, int out_size)
{
    const float* x       = (const float*)d_in[0];
    const float* noise   = (const float*)d_in[1];
    const float* ln1_g   = (const float*)d_in[2];
    const float* ln1_b   = (const float*)d_in[3];
    const float* qkv_w   = (const float*)d_in[4];
    const float* proj_w  = (const float*)d_in[5];
    const float* proj_b  = (const float*)d_in[6];
    const float* ln2_g   = (const float*)d_in[7];
    const float* ln2_b   = (const float*)d_in[8];
    const float* route_w = (const float*)d_in[9];
    const float* route_b = (const float*)d_in[10];
    const float* rln_g   = (const float*)d_in[11];
    const float* rln_b   = (const float*)d_in[12];
    const float* exp_w   = (const float*)d_in[13];
    const float* exp_b   = (const float*)d_in[14];
    float* out = (float*)d_out;

    float *h1, *qkv, *o, *h2;
    cudaGetSymbolAddress((void**)&h1,  g_h1);
    cudaGetSymbolAddress((void**)&qkv, g_qkv);
    cudaGetSymbolAddress((void**)&o,   g_o);
    cudaGetSymbolAddress((void**)&h2,  g_h2);

    cudaFuncSetAttribute(attn_kernel, cudaFuncAttributeMaxDynamicSharedMemorySize, (int)ATTN_SMEM);

    // 1) LN1
    ln_kernel<<<TT, 256>>>(x, ln1_g, ln1_b, h1);
    // 2) QKV GEMM: [T,768] @ [768,2304]
    tf32_gemm_kernel<false><<<dim3(3 * CC / BN, TT / BM), 256>>>(h1, qkv_w, qkv, 3 * CC, CC, nullptr, nullptr);
    // 3) attention
    attn_kernel<<<dim3(NN / 64, BB * HH), 256, ATTN_SMEM>>>(qkv, o);
    // 4) proj + bias + residual -> d_out
    tf32_gemm_kernel<false><<<dim3(CC / BN, TT / BM), 256>>>(o, proj_w, out, CC, CC, proj_b, x);
    // 5) LN2
    ln_kernel<<<TT, 256>>>(out, ln2_g, ln2_b, h2);
    // 6) routing
    zero_cnt_kernel<<<1, 32>>>();
    route_kernel<<<TT / 8, 256>>>(h2, route_w, route_b, rln_g, rln_b, noise);
    // 7) MoE grouped GEMM, accumulates into d_out
    tf32_gemm_kernel<true><<<dim3(CC / BN, TT / BM, EE), 256>>>(h2, exp_w, out, CC, CC, exp_b, nullptr);
}

// round 3
// speedup vs baseline: 2.3913x; 1.7140x over previous
#include <cuda_runtime.h>
#include <math.h>

#define BB 16
#define NN 1024
#define CC 768
#define HH 12
#define DH 64
#define EE 8
#define TT (BB*NN)

// ---------------- scratch (no allocations allowed) ----------------
__device__ float g_h1[(size_t)TT * CC];        // LN1 output
__device__ float g_qkv[(size_t)TT * 3 * CC];   // QKV
__device__ float g_o[(size_t)TT * CC];         // attention output
__device__ float g_h2[(size_t)TT * CC];        // LN2 output
__device__ int   g_cnt[EE];
__device__ int   g_list[EE * TT];
__device__ float g_wt[EE * TT];

__device__ __forceinline__ unsigned f2tf(float f) {
    unsigned u; asm("cvt.rna.tf32.f32 %0, %1;" : "=r"(u) : "f"(f)); return u;
}

__device__ __forceinline__ void mma8(float* c, const unsigned* a, const unsigned* b) {
    asm volatile("mma.sync.aligned.m16n8k8.row.col.f32.tf32.tf32.f32 "
        "{%0,%1,%2,%3}, {%4,%5,%6,%7}, {%8,%9}, {%0,%1,%2,%3};"
        : "+f"(c[0]), "+f"(c[1]), "+f"(c[2]), "+f"(c[3])
        : "r"(a[0]), "r"(a[1]), "r"(a[2]), "r"(a[3]), "r"(b[0]), "r"(b[1]));
}

// ---------------- LayerNorm ----------------
__global__ __launch_bounds__(256) void ln_kernel(const float* __restrict__ in,
    const float* __restrict__ gamma, const float* __restrict__ beta,
    float* __restrict__ out)
{
    int t = blockIdx.x;
    const float* row = in + (size_t)t * CC;
    float s = 0.f, s2 = 0.f;
    for (int i = threadIdx.x; i < CC; i += 256) { float v = row[i]; s += v; s2 += v * v; }
    __shared__ float sh[64];
    #pragma unroll
    for (int o = 16; o > 0; o >>= 1) { s += __shfl_xor_sync(~0u, s, o); s2 += __shfl_xor_sync(~0u, s2, o); }
    int w = threadIdx.x >> 5, l = threadIdx.x & 31;
    if (l == 0) { sh[w] = s; sh[32 + w] = s2; }
    __syncthreads();
    if (threadIdx.x == 0) {
        float a = 0.f, b = 0.f;
        #pragma unroll
        for (int i = 0; i < 8; i++) { a += sh[i]; b += sh[32 + i]; }
        sh[0] = a; sh[1] = b;
    }
    __syncthreads();
    float mean = sh[0] * (1.f / CC);
    float var  = sh[1] * (1.f / CC) - mean * mean;
    float rstd = rsqrtf(var + 1e-5f);
    float* orow = out + (size_t)t * CC;
    for (int i = threadIdx.x; i < CC; i += 256)
        orow[i] = (row[i] - mean) * rstd * gamma[i] + beta[i];
}

// ---------------- TF32 tensor-core GEMM 128x128x16 ----------------
#define BM 128
#define BN 128
#define BK 16
#define ASTR (BM + 8)
#define BSTR (BN + 8)

template<bool MOE>
__global__ __launch_bounds__(256) void tf32_gemm_kernel(
    const float* __restrict__ A, const float* __restrict__ Bm, float* __restrict__ Cm,
    int Nn, int K,
    const float* __restrict__ bias, const float* __restrict__ resid)
{
    __shared__ unsigned As[2][BK][ASTR];
    __shared__ unsigned Bs[2][BK][BSTR];
    __shared__ int   stok[BM];
    __shared__ float swt[BM];

    int bm = blockIdx.y * BM, bn = blockIdx.x * BN;
    int tid = threadIdx.x;
    int e = 0, cnt = 0;
    if (MOE) {
        e = blockIdx.z;
        cnt = g_cnt[e];
        if (bm >= cnt) return;
        if (tid < BM) {
            int m = bm + tid;
            if (m < cnt) { stok[tid] = g_list[e * TT + m]; swt[tid] = g_wt[e * TT + m]; }
            else         { stok[tid] = -1; swt[tid] = 0.f; }
        }
        __syncthreads();
    }

    int lrowA = tid & 127;
    int kcolA = (tid >> 7) * 8;
    const float* Aptr;
    if (MOE) {
        int tok = stok[lrowA];
        Aptr = (tok >= 0) ? A + (size_t)tok * K + kcolA : nullptr;
    } else {
        Aptr = A + (size_t)(bm + lrowA) * K + kcolA;
    }
    int rowB = tid >> 5;
    int colB = (tid & 31) << 2;
    const float* Bbase = MOE ? (Bm + (size_t)e * K * Nn) : Bm;
    const float* Bptr = Bbase + (size_t)rowB * Nn + bn + colB;

    float4 pa0, pa1, pb0, pb1;
    const float4 z4 = make_float4(0.f, 0.f, 0.f, 0.f);

    pa0 = Aptr ? *(const float4*)(Aptr + 0) : z4;
    pa1 = Aptr ? *(const float4*)(Aptr + 4) : z4;
    pb0 = *(const float4*)(Bptr);
    pb1 = *(const float4*)(Bptr + (size_t)8 * Nn);

    {
        As[0][kcolA + 0][lrowA] = f2tf(pa0.x); As[0][kcolA + 1][lrowA] = f2tf(pa0.y);
        As[0][kcolA + 2][lrowA] = f2tf(pa0.z); As[0][kcolA + 3][lrowA] = f2tf(pa0.w);
        As[0][kcolA + 4][lrowA] = f2tf(pa1.x); As[0][kcolA + 5][lrowA] = f2tf(pa1.y);
        As[0][kcolA + 6][lrowA] = f2tf(pa1.z); As[0][kcolA + 7][lrowA] = f2tf(pa1.w);
        uint4 u0 = make_uint4(f2tf(pb0.x), f2tf(pb0.y), f2tf(pb0.z), f2tf(pb0.w));
        uint4 u1 = make_uint4(f2tf(pb1.x), f2tf(pb1.y), f2tf(pb1.z), f2tf(pb1.w));
        *(uint4*)&Bs[0][rowB][colB] = u0;
        *(uint4*)&Bs[0][rowB + 8][colB] = u1;
    }
    __syncthreads();

    int lane = tid & 31, wid = tid >> 5;
    int wm = (wid & 3) * 32;
    int wn = (wid >> 2) * 64;
    int g = lane >> 2, c = lane & 3;

    float acc[2][8][4];
    #pragma unroll
    for (int mi = 0; mi < 2; mi++)
        #pragma unroll
        for (int ni = 0; ni < 8; ni++)
            #pragma unroll
            for (int q = 0; q < 4; q++) acc[mi][ni][q] = 0.f;

    int nIter = K / BK;
    for (int it = 0; it < nIter; it++) {
        int cur = it & 1, nxt = cur ^ 1;
        int k0n = (it + 1) * BK;
        if (it + 1 < nIter) {
            pa0 = Aptr ? *(const float4*)(Aptr + k0n) : z4;
            pa1 = Aptr ? *(const float4*)(Aptr + k0n + 4) : z4;
            pb0 = *(const float4*)(Bptr + (size_t)k0n * Nn);
            pb1 = *(const float4*)(Bptr + (size_t)(k0n + 8) * Nn);
        }

        #pragma unroll
        for (int kk = 0; kk < BK; kk += 8) {
            unsigned af[2][4], bf[8][2];
            #pragma unroll
            for (int mi = 0; mi < 2; mi++) {
                af[mi][0] = As[cur][kk + c][wm + mi * 16 + g];
                af[mi][1] = As[cur][kk + c][wm + mi * 16 + g + 8];
                af[mi][2] = As[cur][kk + c + 4][wm + mi * 16 + g];
                af[mi][3] = As[cur][kk + c + 4][wm + mi * 16 + g + 8];
            }
            #pragma unroll
            for (int ni = 0; ni < 8; ni++) {
                bf[ni][0] = Bs[cur][kk + c][wn + ni * 8 + g];
                bf[ni][1] = Bs[cur][kk + c + 4][wn + ni * 8 + g];
            }
            #pragma unroll
            for (int mi = 0; mi < 2; mi++)
                #pragma unroll
                for (int ni = 0; ni < 8; ni++)
                    mma8(acc[mi][ni], af[mi], bf[ni]);
        }

        if (it + 1 < nIter) {
            As[nxt][kcolA + 0][lrowA] = f2tf(pa0.x); As[nxt][kcolA + 1][lrowA] = f2tf(pa0.y);
            As[nxt][kcolA + 2][lrowA] = f2tf(pa0.z); As[nxt][kcolA + 3][lrowA] = f2tf(pa0.w);
            As[nxt][kcolA + 4][lrowA] = f2tf(pa1.x); As[nxt][kcolA + 5][lrowA] = f2tf(pa1.y);
            As[nxt][kcolA + 6][lrowA] = f2tf(pa1.z); As[nxt][kcolA + 7][lrowA] = f2tf(pa1.w);
            uint4 u0 = make_uint4(f2tf(pb0.x), f2tf(pb0.y), f2tf(pb0.z), f2tf(pb0.w));
            uint4 u1 = make_uint4(f2tf(pb1.x), f2tf(pb1.y), f2tf(pb1.z), f2tf(pb1.w));
            *(uint4*)&Bs[nxt][rowB][colB] = u0;
            *(uint4*)&Bs[nxt][rowB + 8][colB] = u1;
        }
        __syncthreads();
    }

    #pragma unroll
    for (int mi = 0; mi < 2; mi++) {
        int rl0 = wm + mi * 16 + g;
        int rl1 = rl0 + 8;
        if (MOE) {
            int tk0 = stok[rl0], tk1 = stok[rl1];
            float w0 = swt[rl0], w1 = swt[rl1];
            #pragma unroll
            for (int ni = 0; ni < 8; ni++) {
                int cn = bn + wn + ni * 8 + 2 * c;
                float b0 = bias[(size_t)e * Nn + cn], b1 = bias[(size_t)e * Nn + cn + 1];
                if (tk0 >= 0) {
                    float* p = Cm + (size_t)tk0 * Nn + cn;
                    atomicAdd(p,     w0 * (acc[mi][ni][0] + b0));
                    atomicAdd(p + 1, w0 * (acc[mi][ni][1] + b1));
                }
                if (tk1 >= 0) {
                    float* p = Cm + (size_t)tk1 * Nn + cn;
                    atomicAdd(p,     w1 * (acc[mi][ni][2] + b0));
                    atomicAdd(p + 1, w1 * (acc[mi][ni][3] + b1));
                }
            }
        } else {
            int r0 = bm + rl0, r1 = bm + rl1;
            #pragma unroll
            for (int ni = 0; ni < 8; ni++) {
                int cn = bn + wn + ni * 8 + 2 * c;
                float2 v0 = make_float2(acc[mi][ni][0], acc[mi][ni][1]);
                float2 v1 = make_float2(acc[mi][ni][2], acc[mi][ni][3]);
                if (bias) {
                    float b0 = bias[cn], b1 = bias[cn + 1];
                    v0.x += b0; v0.y += b1; v1.x += b0; v1.y += b1;
                }
                if (resid) {
                    float2 r0v = *(const float2*)(resid + (size_t)r0 * Nn + cn);
                    float2 r1v = *(const float2*)(resid + (size_t)r1 * Nn + cn);
                    v0.x += r0v.x; v0.y += r0v.y; v1.x += r1v.x; v1.y += r1v.y;
                }
                *(float2*)(Cm + (size_t)r0 * Nn + cn) = v0;
                *(float2*)(Cm + (size_t)r1 * Nn + cn) = v1;
            }
        }
    }
}

// ---------------- TF32 tensor-core flash attention ----------------
// grid (NN/128, BB*HH); 256 threads (8 warps, warp = 16 q-rows)
// smem (dyn): QP[64][136] (Q staging d-major, then P kv-major)
//             Ks[2][64][72] (d-major), Vs[2][64][72] (token-major)
#define QPSTR 136
#define KVSTR 72
#define ATTN_SMEM ((64*QPSTR + 2*64*KVSTR + 2*64*KVSTR) * 4)

__global__ __launch_bounds__(256, 1) void attn_tc_kernel(const float* __restrict__ qkv,
                                                         float* __restrict__ o)
{
    extern __shared__ unsigned smem_u[];
    unsigned* QP = smem_u;                    // 64 x QPSTR
    unsigned* Ksm = QP + 64 * QPSTR;          // 2 x 64 x KVSTR
    unsigned* Vsm = Ksm + 2 * 64 * KVSTR;     // 2 x 64 x KVSTR

    int bh = blockIdx.y;
    int bb = bh / HH, hh = bh % HH;
    int q0 = blockIdx.x * 128;
    int tid = threadIdx.x;
    int lane = tid & 31, wid = tid >> 5;
    int wm = wid * 16;
    int g = lane >> 2, c = lane & 3;
    const float scale = 0.125f;
    size_t tok0 = (size_t)bb * NN;

    // ---- stage Q (scaled) into QP as [d][row] ----
    #pragma unroll
    for (int it = 0; it < 8; it++) {
        int idx = tid + it * 256;          // 0..2047
        int row = idx & 127;
        int d4 = (idx >> 7) << 2;          // 0..60
        size_t t = tok0 + q0 + row;
        float4 v = *(const float4*)&qkv[((t * 3 + 0) * HH + hh) * DH + d4];
        QP[(d4 + 0) * QPSTR + row] = f2tf(v.x * scale);
        QP[(d4 + 1) * QPSTR + row] = f2tf(v.y * scale);
        QP[(d4 + 2) * QPSTR + row] = f2tf(v.z * scale);
        QP[(d4 + 3) * QPSTR + row] = f2tf(v.w * scale);
    }
    __syncthreads();

    // ---- Q fragments to registers ----
    unsigned qf[8][4];
    #pragma unroll
    for (int kc = 0; kc < 8; kc++) {
        qf[kc][0] = QP[(kc * 8 + c) * QPSTR + wm + g];
        qf[kc][1] = QP[(kc * 8 + c) * QPSTR + wm + g + 8];
        qf[kc][2] = QP[(kc * 8 + c + 4) * QPSTR + wm + g];
        qf[kc][3] = QP[(kc * 8 + c + 4) * QPSTR + wm + g + 8];
    }
    __syncthreads();   // QP now free for P

    float oacc[8][4];
    #pragma unroll
    for (int ni = 0; ni < 8; ni++)
        #pragma unroll
        for (int q = 0; q < 4; q++) oacc[ni][q] = 0.f;
    float m0 = -1e30f, m1 = -1e30f, l0 = 0.f, l1 = 0.f;

    float4 kreg[4], vreg[4];
    // prefetch tile 0
    #pragma unroll
    for (int it = 0; it < 4; it++) {
        int idx = tid + it * 256;
        int token = idx & 63, d4 = (idx >> 6) << 2;
        size_t t = tok0 + 0 + token;
        kreg[it] = *(const float4*)&qkv[((t * 3 + 1) * HH + hh) * DH + d4];
        vreg[it] = *(const float4*)&qkv[((t * 3 + 2) * HH + hh) * DH + d4];
    }
    // store tile 0 to buffer 0
    #pragma unroll
    for (int it = 0; it < 4; it++) {
        int idx = tid + it * 256;
        int token = idx & 63, d4 = (idx >> 6) << 2;
        Ksm[(d4 + 0) * KVSTR + token] = f2tf(kreg[it].x);
        Ksm[(d4 + 1) * KVSTR + token] = f2tf(kreg[it].y);
        Ksm[(d4 + 2) * KVSTR + token] = f2tf(kreg[it].z);
        Ksm[(d4 + 3) * KVSTR + token] = f2tf(kreg[it].w);
        uint4 u = make_uint4(f2tf(vreg[it].x), f2tf(vreg[it].y), f2tf(vreg[it].z), f2tf(vreg[it].w));
        *(uint4*)&Vsm[token * KVSTR + d4] = u;
    }
    __syncthreads();

    const int NTILES = NN / 64;
    for (int tile = 0; tile < NTILES; tile++) {
        int cur = tile & 1, nxt = cur ^ 1;
        const unsigned* Kb = Ksm + cur * 64 * KVSTR;
        const unsigned* Vb = Vsm + cur * 64 * KVSTR;

        // prefetch next tile into regs
        if (tile + 1 < NTILES) {
            #pragma unroll
            for (int it = 0; it < 4; it++) {
                int idx = tid + it * 256;
                int token = idx & 63, d4 = (idx >> 6) << 2;
                size_t t = tok0 + (tile + 1) * 64 + token;
                kreg[it] = *(const float4*)&qkv[((t * 3 + 1) * HH + hh) * DH + d4];
                vreg[it] = *(const float4*)&qkv[((t * 3 + 2) * HH + hh) * DH + d4];
            }
        }

        // ---- S = Q @ K^T ----
        float sa[8][4];
        #pragma unroll
        for (int ni = 0; ni < 8; ni++)
            #pragma unroll
            for (int q = 0; q < 4; q++) sa[ni][q] = 0.f;
        #pragma unroll
        for (int kc = 0; kc < 8; kc++) {
            unsigned bf[8][2];
            #pragma unroll
            for (int ni = 0; ni < 8; ni++) {
                bf[ni][0] = Kb[(kc * 8 + c) * KVSTR + ni * 8 + g];
                bf[ni][1] = Kb[(kc * 8 + c + 4) * KVSTR + ni * 8 + g];
            }
            #pragma unroll
            for (int ni = 0; ni < 8; ni++)
                mma8(sa[ni], qf[kc], bf[ni]);
        }

        // ---- online softmax ----
        float mx0 = -1e30f, mx1 = -1e30f;
        #pragma unroll
        for (int ni = 0; ni < 8; ni++) {
            mx0 = fmaxf(mx0, fmaxf(sa[ni][0], sa[ni][1]));
            mx1 = fmaxf(mx1, fmaxf(sa[ni][2], sa[ni][3]));
        }
        mx0 = fmaxf(mx0, __shfl_xor_sync(~0u, mx0, 1));
        mx0 = fmaxf(mx0, __shfl_xor_sync(~0u, mx0, 2));
        mx1 = fmaxf(mx1, __shfl_xor_sync(~0u, mx1, 1));
        mx1 = fmaxf(mx1, __shfl_xor_sync(~0u, mx1, 2));
        float mn0 = fmaxf(m0, mx0), mn1 = fmaxf(m1, mx1);
        float al0 = __expf(m0 - mn0), al1 = __expf(m1 - mn1);
        float sum0 = 0.f, sum1 = 0.f;
        __syncwarp();
        #pragma unroll
        for (int ni = 0; ni < 8; ni++) {
            float p00 = __expf(sa[ni][0] - mn0);
            float p01 = __expf(sa[ni][1] - mn0);
            float p10 = __expf(sa[ni][2] - mn1);
            float p11 = __expf(sa[ni][3] - mn1);
            sum0 += p00 + p01; sum1 += p10 + p11;
            int kv = ni * 8 + 2 * c;
            QP[(kv) * QPSTR + wm + g]         = f2tf(p00);
            QP[(kv + 1) * QPSTR + wm + g]     = f2tf(p01);
            QP[(kv) * QPSTR + wm + g + 8]     = f2tf(p10);
            QP[(kv + 1) * QPSTR + wm + g + 8] = f2tf(p11);
        }
        sum0 += __shfl_xor_sync(~0u, sum0, 1);
        sum0 += __shfl_xor_sync(~0u, sum0, 2);
        sum1 += __shfl_xor_sync(~0u, sum1, 1);
        sum1 += __shfl_xor_sync(~0u, sum1, 2);
        l0 = l0 * al0 + sum0; l1 = l1 * al1 + sum1;
        m0 = mn0; m1 = mn1;
        #pragma unroll
        for (int ni = 0; ni < 8; ni++) {
            oacc[ni][0] *= al0; oacc[ni][1] *= al0;
            oacc[ni][2] *= al1; oacc[ni][3] *= al1;
        }
        __syncwarp();

        // ---- O += P @ V ----
        #pragma unroll
        for (int kc = 0; kc < 8; kc++) {
            unsigned af[4];
            af[0] = QP[(kc * 8 + c) * QPSTR + wm + g];
            af[1] = QP[(kc * 8 + c) * QPSTR + wm + g + 8];
            af[2] = QP[(kc * 8 + c + 4) * QPSTR + wm + g];
            af[3] = QP[(kc * 8 + c + 4) * QPSTR + wm + g + 8];
            #pragma unroll
            for (int ni = 0; ni < 8; ni++) {
                unsigned bfv[2];
                bfv[0] = Vb[(kc * 8 + c) * KVSTR + ni * 8 + g];
                bfv[1] = Vb[(kc * 8 + c + 4) * KVSTR + ni * 8 + g];
                mma8(oacc[ni], af, bfv);
            }
        }
        __syncwarp();

        // ---- store next K/V tile ----
        if (tile + 1 < NTILES) {
            unsigned* Kn = Ksm + nxt * 64 * KVSTR;
            unsigned* Vn = Vsm + nxt * 64 * KVSTR;
            #pragma unroll
            for (int it = 0; it < 4; it++) {
                int idx = tid + it * 256;
                int token = idx & 63, d4 = (idx >> 6) << 2;
                Kn[(d4 + 0) * KVSTR + token] = f2tf(kreg[it].x);
                Kn[(d4 + 1) * KVSTR + token] = f2tf(kreg[it].y);
                Kn[(d4 + 2) * KVSTR + token] = f2tf(kreg[it].z);
                Kn[(d4 + 3) * KVSTR + token] = f2tf(kreg[it].w);
                uint4 u = make_uint4(f2tf(vreg[it].x), f2tf(vreg[it].y), f2tf(vreg[it].z), f2tf(vreg[it].w));
                *(uint4*)&Vn[token * KVSTR + d4] = u;
            }
        }
        __syncthreads();
    }

    // ---- write O ----
    float inv0 = 1.f / l0, inv1 = 1.f / l1;
    size_t t0 = tok0 + q0 + wm + g;
    size_t t1 = t0 + 8;
    #pragma unroll
    for (int ni = 0; ni < 8; ni++) {
        int d = hh * DH + ni * 8 + 2 * c;
        *(float2*)&o[t0 * CC + d] = make_float2(oacc[ni][0] * inv0, oacc[ni][1] * inv0);
        *(float2*)&o[t1 * CC + d] = make_float2(oacc[ni][2] * inv1, oacc[ni][3] * inv1);
    }
}

// ---------------- router ----------------
__global__ __launch_bounds__(256) void route_kernel(
    const float* __restrict__ h2, const float* __restrict__ route_w,
    const float* __restrict__ route_b, const float* __restrict__ rln_g,
    const float* __restrict__ rln_b, const float* __restrict__ noise)
{
    int warp = threadIdx.x >> 5, lane = threadIdx.x & 31;
    int t = blockIdx.x * 8 + warp;
    const float* hrow = h2 + (size_t)t * CC;
    float acc[EE];
    #pragma unroll
    for (int e = 0; e < EE; e++) acc[e] = 0.f;
    for (int c = lane; c < CC; c += 32) {
        float hv = hrow[c];
        const float* rw = route_w + (size_t)c * EE;
        #pragma unroll
        for (int e = 0; e < EE; e++) acc[e] += hv * rw[e];
    }
    #pragma unroll
    for (int e = 0; e < EE; e++)
        #pragma unroll
        for (int off = 16; off > 0; off >>= 1)
            acc[e] += __shfl_xor_sync(~0u, acc[e], off);

    if (lane == 0) {
        float lg[EE];
        float mean = 0.f;
        #pragma unroll
        for (int e = 0; e < EE; e++) { lg[e] = acc[e] + route_b[e]; mean += lg[e]; }
        mean *= (1.f / EE);
        float var = 0.f;
        #pragma unroll
        for (int e = 0; e < EE; e++) { float d = lg[e] - mean; var += d * d; }
        var *= (1.f / EE);
        float rstd = rsqrtf(var + 1e-5f);
        float mx = -1e30f;
        #pragma unroll
        for (int e = 0; e < EE; e++) { lg[e] = (lg[e] - mean) * rstd * rln_g[e] + rln_b[e]; mx = fmaxf(mx, lg[e]); }
        float den = 0.f;
        float r[EE];
        #pragma unroll
        for (int e = 0; e < EE; e++) { r[e] = __expf(lg[e] - mx); den += r[e]; }
        float inv = 1.f / den;
        const float* nrow = noise + (size_t)t * EE;
        #pragma unroll
        for (int e = 0; e < EE; e++) r[e] = r[e] * inv + nrow[e] * 0.125f;

        int i1 = 0;
        #pragma unroll
        for (int e = 1; e < EE; e++) if (r[e] > r[i1]) i1 = e;
        int i2 = (i1 == 0) ? 1 : 0;
        #pragma unroll
        for (int e = 0; e < EE; e++) if (e != i1 && r[e] > r[i2]) i2 = e;

        float vm = fmaxf(r[i1], r[i2]);
        float e1 = __expf(r[i1] - vm), e2 = __expf(r[i2] - vm);
        float wsum = 1.f / (e1 + e2);
        float w1 = e1 * wsum, w2 = e2 * wsum;

        int p1 = atomicAdd(&g_cnt[i1], 1);
        g_list[i1 * TT + p1] = t; g_wt[i1 * TT + p1] = w1;
        int p2 = atomicAdd(&g_cnt[i2], 1);
        g_list[i2 * TT + p2] = t; g_wt[i2 * TT + p2] = w2;
    }
}

__global__ void zero_cnt_kernel() { if (threadIdx.x < EE) g_cnt[threadIdx.x] = 0; }

// ---------------- launch ----------------
extern "C" void kernel_launch(void* const* d_in, const int* in_sizes, int n_in,
                              void* d_out, int out_size)
{
    const float* x       = (const float*)d_in[0];
    const float* noise   = (const float*)d_in[1];
    const float* ln1_g   = (const float*)d_in[2];
    const float* ln1_b   = (const float*)d_in[3];
    const float* qkv_w   = (const float*)d_in[4];
    const float* proj_w  = (const float*)d_in[5];
    const float* proj_b  = (const float*)d_in[6];
    const float* ln2_g   = (const float*)d_in[7];
    const float* ln2_b   = (const float*)d_in[8];
    const float* route_w = (const float*)d_in[9];
    const float* route_b = (const float*)d_in[10];
    const float* rln_g   = (const float*)d_in[11];
    const float* rln_b   = (const float*)d_in[12];
    const float* exp_w   = (const float*)d_in[13];
    const float* exp_b   = (const float*)d_in[14];
    float* out = (float*)d_out;

    float *h1, *qkv, *o, *h2;
    cudaGetSymbolAddress((void**)&h1,  g_h1);
    cudaGetSymbolAddress((void**)&qkv, g_qkv);
    cudaGetSymbolAddress((void**)&o,   g_o);
    cudaGetSymbolAddress((void**)&h2,  g_h2);

    cudaFuncSetAttribute(attn_tc_kernel, cudaFuncAttributeMaxDynamicSharedMemorySize, (int)ATTN_SMEM);

    // 1) LN1
    ln_kernel<<<TT, 256>>>(x, ln1_g, ln1_b, h1);
    // 2) QKV GEMM
    tf32_gemm_kernel<false><<<dim3(3 * CC / BN, TT / BM), 256>>>(h1, qkv_w, qkv, 3 * CC, CC, nullptr, nullptr);
    // 3) attention (TF32 tensor cores)
    attn_tc_kernel<<<dim3(NN / 128, BB * HH), 256, ATTN_SMEM>>>(qkv, o);
    // 4) proj + bias + residual -> d_out
    tf32_gemm_kernel<false><<<dim3(CC / BN, TT / BM), 256>>>(o, proj_w, out, CC, CC, proj_b, x);
    // 5) LN2
    ln_kernel<<<TT, 256>>>(out, ln2_g, ln2_b, h2);
    // 6) routing
    zero_cnt_kernel<<<1, 32>>>();
    route_kernel<<<TT / 8, 256>>>(h2, route_w, route_b, rln_g, rln_b, noise);
    // 7) MoE grouped GEMM, accumulates into d_out
    tf32_gemm_kernel<true><<<dim3(CC / BN, TT / BM, EE), 256>>>(h2, exp_w, out, CC, CC, exp_b, nullptr);
}

// round 4
// speedup vs baseline: 2.4239x; 1.0136x over previous
#include <cuda_runtime.h>
#include <math.h>

#define BB 16
#define NN 1024
#define CC 768
#define HH 12
#define DH 64
#define EE 8
#define TT (BB*NN)

// ---------------- scratch (no allocations allowed) ----------------
__device__ float g_h1[(size_t)TT * CC];        // LN1 output
__device__ float g_qkv[(size_t)TT * 3 * CC];   // QKV
__device__ float g_o[(size_t)TT * CC];         // attention output
__device__ float g_h2[(size_t)TT * CC];        // LN2 output
__device__ int   g_cnt[EE];
__device__ int   g_list[EE * TT];
__device__ float g_wt[EE * TT];

__device__ __forceinline__ unsigned f2tf(float f) {
    unsigned u; asm("cvt.rna.tf32.f32 %0, %1;" : "=r"(u) : "f"(f)); return u;
}

__device__ __forceinline__ void mma8(float* c, const unsigned* a, const unsigned* b) {
    asm volatile("mma.sync.aligned.m16n8k8.row.col.f32.tf32.tf32.f32 "
        "{%0,%1,%2,%3}, {%4,%5,%6,%7}, {%8,%9}, {%0,%1,%2,%3};"
        : "+f"(c[0]), "+f"(c[1]), "+f"(c[2]), "+f"(c[3])
        : "r"(a[0]), "r"(a[1]), "r"(a[2]), "r"(a[3]), "r"(b[0]), "r"(b[1]));
}

// ---------------- LayerNorm ----------------
__global__ __launch_bounds__(256) void ln_kernel(const float* __restrict__ in,
    const float* __restrict__ gamma, const float* __restrict__ beta,
    float* __restrict__ out)
{
    int t = blockIdx.x;
    const float* row = in + (size_t)t * CC;
    float s = 0.f, s2 = 0.f;
    for (int i = threadIdx.x; i < CC; i += 256) { float v = row[i]; s += v; s2 += v * v; }
    __shared__ float sh[64];
    #pragma unroll
    for (int o = 16; o > 0; o >>= 1) { s += __shfl_xor_sync(~0u, s, o); s2 += __shfl_xor_sync(~0u, s2, o); }
    int w = threadIdx.x >> 5, l = threadIdx.x & 31;
    if (l == 0) { sh[w] = s; sh[32 + w] = s2; }
    __syncthreads();
    if (threadIdx.x == 0) {
        float a = 0.f, b = 0.f;
        #pragma unroll
        for (int i = 0; i < 8; i++) { a += sh[i]; b += sh[32 + i]; }
        sh[0] = a; sh[1] = b;
    }
    __syncthreads();
    float mean = sh[0] * (1.f / CC);
    float var  = sh[1] * (1.f / CC) - mean * mean;
    float rstd = rsqrtf(var + 1e-5f);
    float* orow = out + (size_t)t * CC;
    for (int i = threadIdx.x; i < CC; i += 256)
        orow[i] = (row[i] - mean) * rstd * gamma[i] + beta[i];
}

// ---------------- TF32 tensor-core GEMM 128x128x16 ----------------
#define BM 128
#define BN 128
#define BK 16
#define ASTR (BM + 8)
#define BSTR (BN + 8)

template<bool MOE>
__global__ __launch_bounds__(256, 2) void tf32_gemm_kernel(
    const float* __restrict__ A, const float* __restrict__ Bm, float* __restrict__ Cm,
    int Nn, int K,
    const float* __restrict__ bias, const float* __restrict__ resid)
{
    __shared__ unsigned As[2][BK][ASTR];
    __shared__ unsigned Bs[2][BK][BSTR];
    __shared__ int   stok[BM];
    __shared__ float swt[BM];

    int bm = blockIdx.y * BM, bn = blockIdx.x * BN;
    int tid = threadIdx.x;
    int e = 0, cnt = 0;
    if (MOE) {
        e = blockIdx.z;
        cnt = g_cnt[e];
        if (bm >= cnt) return;
        if (tid < BM) {
            int m = bm + tid;
            if (m < cnt) { stok[tid] = g_list[e * TT + m]; swt[tid] = g_wt[e * TT + m]; }
            else         { stok[tid] = -1; swt[tid] = 0.f; }
        }
        __syncthreads();
    }

    int lrowA = tid & 127;
    int kcolA = (tid >> 7) * 8;
    const float* Aptr;
    if (MOE) {
        int tok = stok[lrowA];
        Aptr = (tok >= 0) ? A + (size_t)tok * K + kcolA : nullptr;
    } else {
        Aptr = A + (size_t)(bm + lrowA) * K + kcolA;
    }
    int rowB = tid >> 5;
    int colB = (tid & 31) << 2;
    const float* Bbase = MOE ? (Bm + (size_t)e * K * Nn) : Bm;
    const float* Bptr = Bbase + (size_t)rowB * Nn + bn + colB;

    float4 pa0, pa1, pb0, pb1;
    const float4 z4 = make_float4(0.f, 0.f, 0.f, 0.f);

    pa0 = Aptr ? *(const float4*)(Aptr + 0) : z4;
    pa1 = Aptr ? *(const float4*)(Aptr + 4) : z4;
    pb0 = *(const float4*)(Bptr);
    pb1 = *(const float4*)(Bptr + (size_t)8 * Nn);

    {
        As[0][kcolA + 0][lrowA] = f2tf(pa0.x); As[0][kcolA + 1][lrowA] = f2tf(pa0.y);
        As[0][kcolA + 2][lrowA] = f2tf(pa0.z); As[0][kcolA + 3][lrowA] = f2tf(pa0.w);
        As[0][kcolA + 4][lrowA] = f2tf(pa1.x); As[0][kcolA + 5][lrowA] = f2tf(pa1.y);
        As[0][kcolA + 6][lrowA] = f2tf(pa1.z); As[0][kcolA + 7][lrowA] = f2tf(pa1.w);
        uint4 u0 = make_uint4(f2tf(pb0.x), f2tf(pb0.y), f2tf(pb0.z), f2tf(pb0.w));
        uint4 u1 = make_uint4(f2tf(pb1.x), f2tf(pb1.y), f2tf(pb1.z), f2tf(pb1.w));
        *(uint4*)&Bs[0][rowB][colB] = u0;
        *(uint4*)&Bs[0][rowB + 8][colB] = u1;
    }
    __syncthreads();

    int lane = tid & 31, wid = tid >> 5;
    int wm = (wid & 3) * 32;
    int wn = (wid >> 2) * 64;
    int g = lane >> 2, c = lane & 3;

    float acc[2][8][4];
    #pragma unroll
    for (int mi = 0; mi < 2; mi++)
        #pragma unroll
        for (int ni = 0; ni < 8; ni++)
            #pragma unroll
            for (int q = 0; q < 4; q++) acc[mi][ni][q] = 0.f;

    int nIter = K / BK;
    for (int it = 0; it < nIter; it++) {
        int cur = it & 1, nxt = cur ^ 1;
        int k0n = (it + 1) * BK;
        if (it + 1 < nIter) {
            pa0 = Aptr ? *(const float4*)(Aptr + k0n) : z4;
            pa1 = Aptr ? *(const float4*)(Aptr + k0n + 4) : z4;
            pb0 = *(const float4*)(Bptr + (size_t)k0n * Nn);
            pb1 = *(const float4*)(Bptr + (size_t)(k0n + 8) * Nn);
        }

        // interleaved frag-load + mma: per ni load 2 B frags then 2 mma
        #pragma unroll
        for (int kk = 0; kk < BK; kk += 8) {
            unsigned af[2][4];
            #pragma unroll
            for (int mi = 0; mi < 2; mi++) {
                af[mi][0] = As[cur][kk + c][wm + mi * 16 + g];
                af[mi][1] = As[cur][kk + c][wm + mi * 16 + g + 8];
                af[mi][2] = As[cur][kk + c + 4][wm + mi * 16 + g];
                af[mi][3] = As[cur][kk + c + 4][wm + mi * 16 + g + 8];
            }
            #pragma unroll
            for (int ni = 0; ni < 8; ni++) {
                unsigned bf[2];
                bf[0] = Bs[cur][kk + c][wn + ni * 8 + g];
                bf[1] = Bs[cur][kk + c + 4][wn + ni * 8 + g];
                mma8(acc[0][ni], af[0], bf);
                mma8(acc[1][ni], af[1], bf);
            }
        }

        if (it + 1 < nIter) {
            As[nxt][kcolA + 0][lrowA] = f2tf(pa0.x); As[nxt][kcolA + 1][lrowA] = f2tf(pa0.y);
            As[nxt][kcolA + 2][lrowA] = f2tf(pa0.z); As[nxt][kcolA + 3][lrowA] = f2tf(pa0.w);
            As[nxt][kcolA + 4][lrowA] = f2tf(pa1.x); As[nxt][kcolA + 5][lrowA] = f2tf(pa1.y);
            As[nxt][kcolA + 6][lrowA] = f2tf(pa1.z); As[nxt][kcolA + 7][lrowA] = f2tf(pa1.w);
            uint4 u0 = make_uint4(f2tf(pb0.x), f2tf(pb0.y), f2tf(pb0.z), f2tf(pb0.w));
            uint4 u1 = make_uint4(f2tf(pb1.x), f2tf(pb1.y), f2tf(pb1.z), f2tf(pb1.w));
            *(uint4*)&Bs[nxt][rowB][colB] = u0;
            *(uint4*)&Bs[nxt][rowB + 8][colB] = u1;
        }
        __syncthreads();
    }

    #pragma unroll
    for (int mi = 0; mi < 2; mi++) {
        int rl0 = wm + mi * 16 + g;
        int rl1 = rl0 + 8;
        if (MOE) {
            int tk0 = stok[rl0], tk1 = stok[rl1];
            float w0 = swt[rl0], w1 = swt[rl1];
            #pragma unroll
            for (int ni = 0; ni < 8; ni++) {
                int cn = bn + wn + ni * 8 + 2 * c;
                float b0 = bias[(size_t)e * Nn + cn], b1 = bias[(size_t)e * Nn + cn + 1];
                if (tk0 >= 0) {
                    float* p = Cm + (size_t)tk0 * Nn + cn;
                    atomicAdd(p,     w0 * (acc[mi][ni][0] + b0));
                    atomicAdd(p + 1, w0 * (acc[mi][ni][1] + b1));
                }
                if (tk1 >= 0) {
                    float* p = Cm + (size_t)tk1 * Nn + cn;
                    atomicAdd(p,     w1 * (acc[mi][ni][2] + b0));
                    atomicAdd(p + 1, w1 * (acc[mi][ni][3] + b1));
                }
            }
        } else {
            int r0 = bm + rl0, r1 = bm + rl1;
            #pragma unroll
            for (int ni = 0; ni < 8; ni++) {
                int cn = bn + wn + ni * 8 + 2 * c;
                float2 v0 = make_float2(acc[mi][ni][0], acc[mi][ni][1]);
                float2 v1 = make_float2(acc[mi][ni][2], acc[mi][ni][3]);
                if (bias) {
                    float b0 = bias[cn], b1 = bias[cn + 1];
                    v0.x += b0; v0.y += b1; v1.x += b0; v1.y += b1;
                }
                if (resid) {
                    float2 r0v = *(const float2*)(resid + (size_t)r0 * Nn + cn);
                    float2 r1v = *(const float2*)(resid + (size_t)r1 * Nn + cn);
                    v0.x += r0v.x; v0.y += r0v.y; v1.x += r1v.x; v1.y += r1v.y;
                }
                *(float2*)(Cm + (size_t)r0 * Nn + cn) = v0;
                *(float2*)(Cm + (size_t)r1 * Nn + cn) = v1;
            }
        }
    }
}

// ---------------- TF32 tensor-core flash attention ----------------
// grid (NN/128, BB*HH); 256 threads (8 warps, warp = 16 q-rows); 2 CTAs/SM
// split K/V prefetch keeps live regs <= 128
#define QPSTR 136
#define KVSTR 72
#define ATTN_SMEM ((64*QPSTR + 2*64*KVSTR + 2*64*KVSTR) * 4)

__global__ __launch_bounds__(256, 2) void attn_tc_kernel(const float* __restrict__ qkv,
                                                         float* __restrict__ o)
{
    extern __shared__ unsigned smem_u[];
    unsigned* QP = smem_u;                    // 64 x QPSTR
    unsigned* Ksm = QP + 64 * QPSTR;          // 2 x 64 x KVSTR
    unsigned* Vsm = Ksm + 2 * 64 * KVSTR;     // 2 x 64 x KVSTR

    int bh = blockIdx.y;
    int bb = bh / HH, hh = bh % HH;
    int q0 = blockIdx.x * 128;
    int tid = threadIdx.x;
    int lane = tid & 31, wid = tid >> 5;
    int wm = wid * 16;
    int g = lane >> 2, c = lane & 3;
    const float scale = 0.125f;
    size_t tok0 = (size_t)bb * NN;

    // per-thread K/V gmem coordinates (64 tokens x 64 dims / 256 threads = 4 float4)
    int kv_token = tid & 63;
    int kv_d4 = (tid >> 6) << 2;     // 0,4,8,12 base; iterates +16

    // ---- stage Q (scaled) into QP as [d][row] ----
    #pragma unroll
    for (int it = 0; it < 8; it++) {
        int idx = tid + it * 256;
        int row = idx & 127;
        int d4 = (idx >> 7) << 2;
        size_t t = tok0 + q0 + row;
        float4 v = *(const float4*)&qkv[((t * 3 + 0) * HH + hh) * DH + d4];
        QP[(d4 + 0) * QPSTR + row] = f2tf(v.x * scale);
        QP[(d4 + 1) * QPSTR + row] = f2tf(v.y * scale);
        QP[(d4 + 2) * QPSTR + row] = f2tf(v.z * scale);
        QP[(d4 + 3) * QPSTR + row] = f2tf(v.w * scale);
    }
    __syncthreads();

    // ---- Q fragments to registers ----
    unsigned qf[8][4];
    #pragma unroll
    for (int kc = 0; kc < 8; kc++) {
        qf[kc][0] = QP[(kc * 8 + c) * QPSTR + wm + g];
        qf[kc][1] = QP[(kc * 8 + c) * QPSTR + wm + g + 8];
        qf[kc][2] = QP[(kc * 8 + c + 4) * QPSTR + wm + g];
        qf[kc][3] = QP[(kc * 8 + c + 4) * QPSTR + wm + g + 8];
    }
    __syncthreads();   // QP now free for P

    float oacc[8][4];
    #pragma unroll
    for (int ni = 0; ni < 8; ni++)
        #pragma unroll
        for (int q = 0; q < 4; q++) oacc[ni][q] = 0.f;
    float m0 = -1e30f, m1 = -1e30f, l0 = 0.f, l1 = 0.f;

    // ---- prime tile 0: K then V (sequential, low reg pressure) ----
    {
        #pragma unroll
        for (int it = 0; it < 4; it++) {
            int token = kv_token, d4 = kv_d4 + it * 16;
            size_t t = tok0 + token;
            float4 kv4 = *(const float4*)&qkv[((t * 3 + 1) * HH + hh) * DH + d4];
            Ksm[(d4 + 0) * KVSTR + token] = f2tf(kv4.x);
            Ksm[(d4 + 1) * KVSTR + token] = f2tf(kv4.y);
            Ksm[(d4 + 2) * KVSTR + token] = f2tf(kv4.z);
            Ksm[(d4 + 3) * KVSTR + token] = f2tf(kv4.w);
        }
        #pragma unroll
        for (int it = 0; it < 4; it++) {
            int token = kv_token, d4 = kv_d4 + it * 16;
            size_t t = tok0 + token;
            float4 vv4 = *(const float4*)&qkv[((t * 3 + 2) * HH + hh) * DH + d4];
            uint4 u = make_uint4(f2tf(vv4.x), f2tf(vv4.y), f2tf(vv4.z), f2tf(vv4.w));
            *(uint4*)&Vsm[token * KVSTR + d4] = u;
        }
    }
    __syncthreads();

    const int NTILES = NN / 64;
    for (int tile = 0; tile < NTILES; tile++) {
        int cur = tile & 1, nxt = cur ^ 1;
        const unsigned* Kb = Ksm + cur * 64 * KVSTR;
        const unsigned* Vb = Vsm + cur * 64 * KVSTR;
        bool more = (tile + 1 < NTILES);

        // prefetch next K into regs (16 regs)
        float4 kreg[4];
        if (more) {
            #pragma unroll
            for (int it = 0; it < 4; it++) {
                size_t t = tok0 + (tile + 1) * 64 + kv_token;
                kreg[it] = *(const float4*)&qkv[((t * 3 + 1) * HH + hh) * DH + kv_d4 + it * 16];
            }
        }

        // ---- S = Q @ K^T ----
        float sa[8][4];
        #pragma unroll
        for (int ni = 0; ni < 8; ni++)
            #pragma unroll
            for (int q = 0; q < 4; q++) sa[ni][q] = 0.f;
        #pragma unroll
        for (int kc = 0; kc < 8; kc++) {
            #pragma unroll
            for (int ni = 0; ni < 8; ni++) {
                unsigned bf[2];
                bf[0] = Kb[(kc * 8 + c) * KVSTR + ni * 8 + g];
                bf[1] = Kb[(kc * 8 + c + 4) * KVSTR + ni * 8 + g];
                mma8(sa[ni], qf[kc], bf);
            }
        }

        // store next K (kreg dies here)
        if (more) {
            unsigned* Kn = Ksm + nxt * 64 * KVSTR;
            #pragma unroll
            for (int it = 0; it < 4; it++) {
                int d4 = kv_d4 + it * 16;
                Kn[(d4 + 0) * KVSTR + kv_token] = f2tf(kreg[it].x);
                Kn[(d4 + 1) * KVSTR + kv_token] = f2tf(kreg[it].y);
                Kn[(d4 + 2) * KVSTR + kv_token] = f2tf(kreg[it].z);
                Kn[(d4 + 3) * KVSTR + kv_token] = f2tf(kreg[it].w);
            }
        }

        // ---- online softmax ----
        float mx0 = -1e30f, mx1 = -1e30f;
        #pragma unroll
        for (int ni = 0; ni < 8; ni++) {
            mx0 = fmaxf(mx0, fmaxf(sa[ni][0], sa[ni][1]));
            mx1 = fmaxf(mx1, fmaxf(sa[ni][2], sa[ni][3]));
        }
        mx0 = fmaxf(mx0, __shfl_xor_sync(~0u, mx0, 1));
        mx0 = fmaxf(mx0, __shfl_xor_sync(~0u, mx0, 2));
        mx1 = fmaxf(mx1, __shfl_xor_sync(~0u, mx1, 1));
        mx1 = fmaxf(mx1, __shfl_xor_sync(~0u, mx1, 2));
        float mn0 = fmaxf(m0, mx0), mn1 = fmaxf(m1, mx1);
        float al0 = __expf(m0 - mn0), al1 = __expf(m1 - mn1);
        float sum0 = 0.f, sum1 = 0.f;
        __syncwarp();
        #pragma unroll
        for (int ni = 0; ni < 8; ni++) {
            float p00 = __expf(sa[ni][0] - mn0);
            float p01 = __expf(sa[ni][1] - mn0);
            float p10 = __expf(sa[ni][2] - mn1);
            float p11 = __expf(sa[ni][3] - mn1);
            sum0 += p00 + p01; sum1 += p10 + p11;
            int kv = ni * 8 + 2 * c;
            QP[(kv) * QPSTR + wm + g]         = f2tf(p00);
            QP[(kv + 1) * QPSTR + wm + g]     = f2tf(p01);
            QP[(kv) * QPSTR + wm + g + 8]     = f2tf(p10);
            QP[(kv + 1) * QPSTR + wm + g + 8] = f2tf(p11);
        }
        sum0 += __shfl_xor_sync(~0u, sum0, 1);
        sum0 += __shfl_xor_sync(~0u, sum0, 2);
        sum1 += __shfl_xor_sync(~0u, sum1, 1);
        sum1 += __shfl_xor_sync(~0u, sum1, 2);
        l0 = l0 * al0 + sum0; l1 = l1 * al1 + sum1;
        m0 = mn0; m1 = mn1;
        #pragma unroll
        for (int ni = 0; ni < 8; ni++) {
            oacc[ni][0] *= al0; oacc[ni][1] *= al0;
            oacc[ni][2] *= al1; oacc[ni][3] *= al1;
        }
        __syncwarp();

        // prefetch next V into regs (16 regs)
        float4 vreg[4];
        if (more) {
            #pragma unroll
            for (int it = 0; it < 4; it++) {
                size_t t = tok0 + (tile + 1) * 64 + kv_token;
                vreg[it] = *(const float4*)&qkv[((t * 3 + 2) * HH + hh) * DH + kv_d4 + it * 16];
            }
        }

        // ---- O += P @ V ----
        #pragma unroll
        for (int kc = 0; kc < 8; kc++) {
            unsigned af[4];
            af[0] = QP[(kc * 8 + c) * QPSTR + wm + g];
            af[1] = QP[(kc * 8 + c) * QPSTR + wm + g + 8];
            af[2] = QP[(kc * 8 + c + 4) * QPSTR + wm + g];
            af[3] = QP[(kc * 8 + c + 4) * QPSTR + wm + g + 8];
            #pragma unroll
            for (int ni = 0; ni < 8; ni++) {
                unsigned bfv[2];
                bfv[0] = Vb[(kc * 8 + c) * KVSTR + ni * 8 + g];
                bfv[1] = Vb[(kc * 8 + c + 4) * KVSTR + ni * 8 + g];
                mma8(oacc[ni], af, bfv);
            }
        }

        // store next V
        if (more) {
            unsigned* Vn = Vsm + nxt * 64 * KVSTR;
            #pragma unroll
            for (int it = 0; it < 4; it++) {
                int d4 = kv_d4 + it * 16;
                uint4 u = make_uint4(f2tf(vreg[it].x), f2tf(vreg[it].y), f2tf(vreg[it].z), f2tf(vreg[it].w));
                *(uint4*)&Vn[kv_token * KVSTR + d4] = u;
            }
        }
        __syncthreads();
    }

    // ---- write O ----
    float inv0 = 1.f / l0, inv1 = 1.f / l1;
    size_t t0 = tok0 + q0 + wm + g;
    size_t t1 = t0 + 8;
    #pragma unroll
    for (int ni = 0; ni < 8; ni++) {
        int d = hh * DH + ni * 8 + 2 * c;
        *(float2*)&o[t0 * CC + d] = make_float2(oacc[ni][0] * inv0, oacc[ni][1] * inv0);
        *(float2*)&o[t1 * CC + d] = make_float2(oacc[ni][2] * inv1, oacc[ni][3] * inv1);
    }
}

// ---------------- router ----------------
__global__ __launch_bounds__(256) void route_kernel(
    const float* __restrict__ h2, const float* __restrict__ route_w,
    const float* __restrict__ route_b, const float* __restrict__ rln_g,
    const float* __restrict__ rln_b, const float* __restrict__ noise)
{
    int warp = threadIdx.x >> 5, lane = threadIdx.x & 31;
    int t = blockIdx.x * 8 + warp;
    const float* hrow = h2 + (size_t)t * CC;
    float acc[EE];
    #pragma unroll
    for (int e = 0; e < EE; e++) acc[e] = 0.f;
    for (int c = lane; c < CC; c += 32) {
        float hv = hrow[c];
        const float* rw = route_w + (size_t)c * EE;
        #pragma unroll
        for (int e = 0; e < EE; e++) acc[e] += hv * rw[e];
    }
    #pragma unroll
    for (int e = 0; e < EE; e++)
        #pragma unroll
        for (int off = 16; off > 0; off >>= 1)
            acc[e] += __shfl_xor_sync(~0u, acc[e], off);

    if (lane == 0) {
        float lg[EE];
        float mean = 0.f;
        #pragma unroll
        for (int e = 0; e < EE; e++) { lg[e] = acc[e] + route_b[e]; mean += lg[e]; }
        mean *= (1.f / EE);
        float var = 0.f;
        #pragma unroll
        for (int e = 0; e < EE; e++) { float d = lg[e] - mean; var += d * d; }
        var *= (1.f / EE);
        float rstd = rsqrtf(var + 1e-5f);
        float mx = -1e30f;
        #pragma unroll
        for (int e = 0; e < EE; e++) { lg[e] = (lg[e] - mean) * rstd * rln_g[e] + rln_b[e]; mx = fmaxf(mx, lg[e]); }
        float den = 0.f;
        float r[EE];
        #pragma unroll
        for (int e = 0; e < EE; e++) { r[e] = __expf(lg[e] - mx); den += r[e]; }
        float inv = 1.f / den;
        const float* nrow = noise + (size_t)t * EE;
        #pragma unroll
        for (int e = 0; e < EE; e++) r[e] = r[e] * inv + nrow[e] * 0.125f;

        int i1 = 0;
        #pragma unroll
        for (int e = 1; e < EE; e++) if (r[e] > r[i1]) i1 = e;
        int i2 = (i1 == 0) ? 1 : 0;
        #pragma unroll
        for (int e = 0; e < EE; e++) if (e != i1 && r[e] > r[i2]) i2 = e;

        float vm = fmaxf(r[i1], r[i2]);
        float e1 = __expf(r[i1] - vm), e2 = __expf(r[i2] - vm);
        float wsum = 1.f / (e1 + e2);
        float w1 = e1 * wsum, w2 = e2 * wsum;

        int p1 = atomicAdd(&g_cnt[i1], 1);
        g_list[i1 * TT + p1] = t; g_wt[i1 * TT + p1] = w1;
        int p2 = atomicAdd(&g_cnt[i2], 1);
        g_list[i2 * TT + p2] = t; g_wt[i2 * TT + p2] = w2;
    }
}

__global__ void zero_cnt_kernel() { if (threadIdx.x < EE) g_cnt[threadIdx.x] = 0; }

// ---------------- launch ----------------
extern "C" void kernel_launch(void* const* d_in, const int* in_sizes, int n_in,
                              void* d_out, int out_size)
{
    const float* x       = (const float*)d_in[0];
    const float* noise   = (const float*)d_in[1];
    const float* ln1_g   = (const float*)d_in[2];
    const float* ln1_b   = (const float*)d_in[3];
    const float* qkv_w   = (const float*)d_in[4];
    const float* proj_w  = (const float*)d_in[5];
    const float* proj_b  = (const float*)d_in[6];
    const float* ln2_g   = (const float*)d_in[7];
    const float* ln2_b   = (const float*)d_in[8];
    const float* route_w = (const float*)d_in[9];
    const float* route_b = (const float*)d_in[10];
    const float* rln_g   = (const float*)d_in[11];
    const float* rln_b   = (const float*)d_in[12];
    const float* exp_w   = (const float*)d_in[13];
    const float* exp_b   = (const float*)d_in[14];
    float* out = (float*)d_out;

    float *h1, *qkv, *o, *h2;
    cudaGetSymbolAddress((void**)&h1,  g_h1);
    cudaGetSymbolAddress((void**)&qkv, g_qkv);
    cudaGetSymbolAddress((void**)&o,   g_o);
    cudaGetSymbolAddress((void**)&h2,  g_h2);

    cudaFuncSetAttribute(attn_tc_kernel, cudaFuncAttributeMaxDynamicSharedMemorySize, (int)ATTN_SMEM);

    // 1) LN1
    ln_kernel<<<TT, 256>>>(x, ln1_g, ln1_b, h1);
    // 2) QKV GEMM
    tf32_gemm_kernel<false><<<dim3(3 * CC / BN, TT / BM), 256>>>(h1, qkv_w, qkv, 3 * CC, CC, nullptr, nullptr);
    // 3) attention (TF32 tensor cores, 2 CTAs/SM)
    attn_tc_kernel<<<dim3(NN / 128, BB * HH), 256, ATTN_SMEM>>>(qkv, o);
    // 4) proj + bias + residual -> d_out
    tf32_gemm_kernel<false><<<dim3(CC / BN, TT / BM), 256>>>(o, proj_w, out, CC, CC, proj_b, x);
    // 5) LN2
    ln_kernel<<<TT, 256>>>(out, ln2_g, ln2_b, h2);
    // 6) routing
    zero_cnt_kernel<<<1, 32>>>();
    route_kernel<<<TT / 8, 256>>>(h2, route_w, route_b, rln_g, rln_b, noise);
    // 7) MoE grouped GEMM, accumulates into d_out
    tf32_gemm_kernel<true><<<dim3(CC / BN, TT / BM, EE), 256>>>(h2, exp_w, out, CC, CC, exp_b, nullptr);
}

// round 5
// speedup vs baseline: 2.7627x; 1.1398x over previous
#include <cuda_runtime.h>
#include <cuda_bf16.h>
#include <math.h>

#define BB 16
#define NN 1024
#define CC 768
#define HH 12
#define DH 64
#define EE 8
#define TT (BB*NN)

// ---------------- scratch (no allocations allowed) ----------------
__device__ float g_h1[(size_t)TT * CC];        // LN1 output
__device__ float g_qkv[(size_t)TT * 3 * CC];   // QKV
__device__ float g_o[(size_t)TT * CC];         // attention output
__device__ float g_h2[(size_t)TT * CC];        // LN2 output
__device__ int   g_cnt[EE];
__device__ int   g_list[EE * TT];
__device__ float g_wt[EE * TT];

__device__ __forceinline__ unsigned f2tf(float f) {
    unsigned u; asm("cvt.rna.tf32.f32 %0, %1;" : "=r"(u) : "f"(f)); return u;
}

__device__ __forceinline__ unsigned f2bf2(float lo, float hi) {
    __nv_bfloat162 h = __floats2bfloat162_rn(lo, hi);
    return *reinterpret_cast<unsigned*>(&h);
}

__device__ __forceinline__ void mma8(float* c, const unsigned* a, const unsigned* b) {
    asm volatile("mma.sync.aligned.m16n8k8.row.col.f32.tf32.tf32.f32 "
        "{%0,%1,%2,%3}, {%4,%5,%6,%7}, {%8,%9}, {%0,%1,%2,%3};"
        : "+f"(c[0]), "+f"(c[1]), "+f"(c[2]), "+f"(c[3])
        : "r"(a[0]), "r"(a[1]), "r"(a[2]), "r"(a[3]), "r"(b[0]), "r"(b[1]));
}

__device__ __forceinline__ void mma16(float* c, const unsigned* a, unsigned b0, unsigned b1) {
    asm volatile("mma.sync.aligned.m16n8k16.row.col.f32.bf16.bf16.f32 "
        "{%0,%1,%2,%3}, {%4,%5,%6,%7}, {%8,%9}, {%0,%1,%2,%3};"
        : "+f"(c[0]), "+f"(c[1]), "+f"(c[2]), "+f"(c[3])
        : "r"(a[0]), "r"(a[1]), "r"(a[2]), "r"(a[3]), "r"(b0), "r"(b1));
}

// ---------------- LayerNorm ----------------
__global__ __launch_bounds__(256) void ln_kernel(const float* __restrict__ in,
    const float* __restrict__ gamma, const float* __restrict__ beta,
    float* __restrict__ out)
{
    int t = blockIdx.x;
    const float* row = in + (size_t)t * CC;
    float s = 0.f, s2 = 0.f;
    for (int i = threadIdx.x; i < CC; i += 256) { float v = row[i]; s += v; s2 += v * v; }
    __shared__ float sh[64];
    #pragma unroll
    for (int o = 16; o > 0; o >>= 1) { s += __shfl_xor_sync(~0u, s, o); s2 += __shfl_xor_sync(~0u, s2, o); }
    int w = threadIdx.x >> 5, l = threadIdx.x & 31;
    if (l == 0) { sh[w] = s; sh[32 + w] = s2; }
    __syncthreads();
    if (threadIdx.x == 0) {
        float a = 0.f, b = 0.f;
        #pragma unroll
        for (int i = 0; i < 8; i++) { a += sh[i]; b += sh[32 + i]; }
        sh[0] = a; sh[1] = b;
    }
    __syncthreads();
    float mean = sh[0] * (1.f / CC);
    float var  = sh[1] * (1.f / CC) - mean * mean;
    float rstd = rsqrtf(var + 1e-5f);
    float* orow = out + (size_t)t * CC;
    for (int i = threadIdx.x; i < CC; i += 256)
        orow[i] = (row[i] - mean) * rstd * gamma[i] + beta[i];
}

// ---------------- TF32 tensor-core GEMM 128x128x16 ----------------
#define BM 128
#define BN 128
#define BK 16
#define ASTR (BM + 8)
#define BSTR (BN + 8)

template<bool MOE>
__global__ __launch_bounds__(256, 2) void tf32_gemm_kernel(
    const float* __restrict__ A, const float* __restrict__ Bm, float* __restrict__ Cm,
    int Nn, int K,
    const float* __restrict__ bias, const float* __restrict__ resid)
{
    __shared__ unsigned As[2][BK][ASTR];
    __shared__ unsigned Bs[2][BK][BSTR];
    __shared__ int   stok[BM];
    __shared__ float swt[BM];

    int bm = blockIdx.y * BM, bn = blockIdx.x * BN;
    int tid = threadIdx.x;
    int e = 0, cnt = 0;
    if (MOE) {
        e = blockIdx.z;
        cnt = g_cnt[e];
        if (bm >= cnt) return;
        if (tid < BM) {
            int m = bm + tid;
            if (m < cnt) { stok[tid] = g_list[e * TT + m]; swt[tid] = g_wt[e * TT + m]; }
            else         { stok[tid] = -1; swt[tid] = 0.f; }
        }
        __syncthreads();
    }

    int lrowA = tid & 127;
    int kcolA = (tid >> 7) * 8;
    const float* Aptr;
    if (MOE) {
        int tok = stok[lrowA];
        Aptr = (tok >= 0) ? A + (size_t)tok * K + kcolA : nullptr;
    } else {
        Aptr = A + (size_t)(bm + lrowA) * K + kcolA;
    }
    int rowB = tid >> 5;
    int colB = (tid & 31) << 2;
    const float* Bbase = MOE ? (Bm + (size_t)e * K * Nn) : Bm;
    const float* Bptr = Bbase + (size_t)rowB * Nn + bn + colB;

    float4 pa0, pa1, pb0, pb1;
    const float4 z4 = make_float4(0.f, 0.f, 0.f, 0.f);

    pa0 = Aptr ? *(const float4*)(Aptr + 0) : z4;
    pa1 = Aptr ? *(const float4*)(Aptr + 4) : z4;
    pb0 = *(const float4*)(Bptr);
    pb1 = *(const float4*)(Bptr + (size_t)8 * Nn);

    {
        As[0][kcolA + 0][lrowA] = f2tf(pa0.x); As[0][kcolA + 1][lrowA] = f2tf(pa0.y);
        As[0][kcolA + 2][lrowA] = f2tf(pa0.z); As[0][kcolA + 3][lrowA] = f2tf(pa0.w);
        As[0][kcolA + 4][lrowA] = f2tf(pa1.x); As[0][kcolA + 5][lrowA] = f2tf(pa1.y);
        As[0][kcolA + 6][lrowA] = f2tf(pa1.z); As[0][kcolA + 7][lrowA] = f2tf(pa1.w);
        uint4 u0 = make_uint4(f2tf(pb0.x), f2tf(pb0.y), f2tf(pb0.z), f2tf(pb0.w));
        uint4 u1 = make_uint4(f2tf(pb1.x), f2tf(pb1.y), f2tf(pb1.z), f2tf(pb1.w));
        *(uint4*)&Bs[0][rowB][colB] = u0;
        *(uint4*)&Bs[0][rowB + 8][colB] = u1;
    }
    __syncthreads();

    int lane = tid & 31, wid = tid >> 5;
    int wm = (wid & 3) * 32;
    int wn = (wid >> 2) * 64;
    int g = lane >> 2, c = lane & 3;

    float acc[2][8][4];
    #pragma unroll
    for (int mi = 0; mi < 2; mi++)
        #pragma unroll
        for (int ni = 0; ni < 8; ni++)
            #pragma unroll
            for (int q = 0; q < 4; q++) acc[mi][ni][q] = 0.f;

    int nIter = K / BK;
    for (int it = 0; it < nIter; it++) {
        int cur = it & 1, nxt = cur ^ 1;
        int k0n = (it + 1) * BK;
        if (it + 1 < nIter) {
            pa0 = Aptr ? *(const float4*)(Aptr + k0n) : z4;
            pa1 = Aptr ? *(const float4*)(Aptr + k0n + 4) : z4;
            pb0 = *(const float4*)(Bptr + (size_t)k0n * Nn);
            pb1 = *(const float4*)(Bptr + (size_t)(k0n + 8) * Nn);
        }

        #pragma unroll
        for (int kk = 0; kk < BK; kk += 8) {
            unsigned af[2][4];
            #pragma unroll
            for (int mi = 0; mi < 2; mi++) {
                af[mi][0] = As[cur][kk + c][wm + mi * 16 + g];
                af[mi][1] = As[cur][kk + c][wm + mi * 16 + g + 8];
                af[mi][2] = As[cur][kk + c + 4][wm + mi * 16 + g];
                af[mi][3] = As[cur][kk + c + 4][wm + mi * 16 + g + 8];
            }
            #pragma unroll
            for (int ni = 0; ni < 8; ni++) {
                unsigned bf[2];
                bf[0] = Bs[cur][kk + c][wn + ni * 8 + g];
                bf[1] = Bs[cur][kk + c + 4][wn + ni * 8 + g];
                mma8(acc[0][ni], af[0], bf);
                mma8(acc[1][ni], af[1], bf);
            }
        }

        if (it + 1 < nIter) {
            As[nxt][kcolA + 0][lrowA] = f2tf(pa0.x); As[nxt][kcolA + 1][lrowA] = f2tf(pa0.y);
            As[nxt][kcolA + 2][lrowA] = f2tf(pa0.z); As[nxt][kcolA + 3][lrowA] = f2tf(pa0.w);
            As[nxt][kcolA + 4][lrowA] = f2tf(pa1.x); As[nxt][kcolA + 5][lrowA] = f2tf(pa1.y);
            As[nxt][kcolA + 6][lrowA] = f2tf(pa1.z); As[nxt][kcolA + 7][lrowA] = f2tf(pa1.w);
            uint4 u0 = make_uint4(f2tf(pb0.x), f2tf(pb0.y), f2tf(pb0.z), f2tf(pb0.w));
            uint4 u1 = make_uint4(f2tf(pb1.x), f2tf(pb1.y), f2tf(pb1.z), f2tf(pb1.w));
            *(uint4*)&Bs[nxt][rowB][colB] = u0;
            *(uint4*)&Bs[nxt][rowB + 8][colB] = u1;
        }
        __syncthreads();
    }

    #pragma unroll
    for (int mi = 0; mi < 2; mi++) {
        int rl0 = wm + mi * 16 + g;
        int rl1 = rl0 + 8;
        if (MOE) {
            int tk0 = stok[rl0], tk1 = stok[rl1];
            float w0 = swt[rl0], w1 = swt[rl1];
            #pragma unroll
            for (int ni = 0; ni < 8; ni++) {
                int cn = bn + wn + ni * 8 + 2 * c;
                float b0 = bias[(size_t)e * Nn + cn], b1 = bias[(size_t)e * Nn + cn + 1];
                if (tk0 >= 0) {
                    float* p = Cm + (size_t)tk0 * Nn + cn;
                    atomicAdd(p,     w0 * (acc[mi][ni][0] + b0));
                    atomicAdd(p + 1, w0 * (acc[mi][ni][1] + b1));
                }
                if (tk1 >= 0) {
                    float* p = Cm + (size_t)tk1 * Nn + cn;
                    atomicAdd(p,     w1 * (acc[mi][ni][2] + b0));
                    atomicAdd(p + 1, w1 * (acc[mi][ni][3] + b1));
                }
            }
        } else {
            int r0 = bm + rl0, r1 = bm + rl1;
            #pragma unroll
            for (int ni = 0; ni < 8; ni++) {
                int cn = bn + wn + ni * 8 + 2 * c;
                float2 v0 = make_float2(acc[mi][ni][0], acc[mi][ni][1]);
                float2 v1 = make_float2(acc[mi][ni][2], acc[mi][ni][3]);
                if (bias) {
                    float b0 = bias[cn], b1 = bias[cn + 1];
                    v0.x += b0; v0.y += b1; v1.x += b0; v1.y += b1;
                }
                if (resid) {
                    float2 r0v = *(const float2*)(resid + (size_t)r0 * Nn + cn);
                    float2 r1v = *(const float2*)(resid + (size_t)r1 * Nn + cn);
                    v0.x += r0v.x; v0.y += r0v.y; v1.x += r1v.x; v1.y += r1v.y;
                }
                *(float2*)(Cm + (size_t)r0 * Nn + cn) = v0;
                *(float2*)(Cm + (size_t)r1 * Nn + cn) = v1;
            }
        }
    }
}

// ---------------- bf16 tensor-core flash attention ----------------
// grid (NN/128, BB*HH); 256 threads (8 warps, warp = 16 q-rows); 2 CTAs/SM
// Layouts (word stride 36 = 72 bf16):
//   QPs [row 0..127][d or kv]  row-major bf16 (Q staging, then P)
//   Ks  [tok 0..63][d]         token-major bf16  (B operand of S = Q K^T)
//   Vs  [d 0..63][tok]         d-major bf16      (B operand of O = P V)
#define QSTRW 36
#define KSTRW 36

__global__ __launch_bounds__(256, 2) void attn_bf16_kernel(const float* __restrict__ qkv,
                                                           float* __restrict__ o)
{
    __shared__ unsigned QPs[128 * QSTRW];   // 18 KB
    __shared__ unsigned Ks[64 * KSTRW];     // 9 KB
    __shared__ unsigned Vs[64 * KSTRW];     // 9 KB

    int bh = blockIdx.y;
    int bb = bh / HH, hh = bh % HH;
    int q0 = blockIdx.x * 128;
    int tid = threadIdx.x;
    int lane = tid & 31, wid = tid >> 5;
    int wm = wid * 16;
    int g = lane >> 2, c = lane & 3;
    const float scale = 0.125f;
    size_t tok0 = (size_t)bb * NN;

    int kv_token = tid & 63;
    int kv_d4b = (tid >> 6) << 2;   // 0,4,8,12 ; +16 per iter

    // ---- stage Q (scaled), row-major bf16 ----
    #pragma unroll
    for (int it = 0; it < 8; it++) {
        int idx = tid + it * 256;
        int row = idx >> 4, d4 = (idx & 15) << 2;
        size_t t = tok0 + q0 + row;
        float4 v = *(const float4*)&qkv[((t * 3 + 0) * HH + hh) * DH + d4];
        QPs[row * QSTRW + (d4 >> 1)]     = f2bf2(v.x * scale, v.y * scale);
        QPs[row * QSTRW + (d4 >> 1) + 1] = f2bf2(v.z * scale, v.w * scale);
    }
    __syncthreads();

    // ---- Q fragments (m16k16 x 4 chunks) ----
    unsigned qf[4][4];
    #pragma unroll
    for (int kc = 0; kc < 4; kc++) {
        int bw = kc * 8 + c;
        qf[kc][0] = QPs[(wm + g) * QSTRW + bw];
        qf[kc][1] = QPs[(wm + g + 8) * QSTRW + bw];
        qf[kc][2] = QPs[(wm + g) * QSTRW + bw + 4];
        qf[kc][3] = QPs[(wm + g + 8) * QSTRW + bw + 4];
    }
    __syncthreads();   // QPs now free for P

    float oacc[8][4];
    #pragma unroll
    for (int ni = 0; ni < 8; ni++)
        #pragma unroll
        for (int q = 0; q < 4; q++) oacc[ni][q] = 0.f;
    float m0 = -1e30f, m1 = -1e30f, l0 = 0.f, l1 = 0.f;

    // ---- prime tile 0 ----
    {
        __nv_bfloat16* Vb = (__nv_bfloat16*)Vs;
        #pragma unroll
        for (int it = 0; it < 4; it++) {
            int d4 = kv_d4b + it * 16;
            size_t t = tok0 + kv_token;
            float4 k4 = *(const float4*)&qkv[((t * 3 + 1) * HH + hh) * DH + d4];
            Ks[kv_token * KSTRW + (d4 >> 1)]     = f2bf2(k4.x, k4.y);
            Ks[kv_token * KSTRW + (d4 >> 1) + 1] = f2bf2(k4.z, k4.w);
            float4 v4 = *(const float4*)&qkv[((t * 3 + 2) * HH + hh) * DH + d4];
            Vb[(d4 + 0) * 72 + kv_token] = __float2bfloat16_rn(v4.x);
            Vb[(d4 + 1) * 72 + kv_token] = __float2bfloat16_rn(v4.y);
            Vb[(d4 + 2) * 72 + kv_token] = __float2bfloat16_rn(v4.z);
            Vb[(d4 + 3) * 72 + kv_token] = __float2bfloat16_rn(v4.w);
        }
    }
    __syncthreads();

    const int NTILES = NN / 64;
    for (int tile = 0; tile < NTILES; tile++) {
        bool more = (tile + 1 < NTILES);

        // prefetch next K into regs
        float4 kreg[4];
        if (more) {
            size_t t = tok0 + (tile + 1) * 64 + kv_token;
            #pragma unroll
            for (int it = 0; it < 4; it++)
                kreg[it] = *(const float4*)&qkv[((t * 3 + 1) * HH + hh) * DH + kv_d4b + it * 16];
        }

        // ---- S = Q @ K^T ----
        float sa[8][4];
        #pragma unroll
        for (int ni = 0; ni < 8; ni++)
            #pragma unroll
            for (int q = 0; q < 4; q++) sa[ni][q] = 0.f;
        #pragma unroll
        for (int kc = 0; kc < 4; kc++) {
            #pragma unroll
            for (int ni = 0; ni < 8; ni++) {
                int bw = (ni * 8 + g) * KSTRW + kc * 8 + c;
                mma16(sa[ni], qf[kc], Ks[bw], Ks[bw + 4]);
            }
        }

        // ---- online softmax + P store (bf16, warp-local rows) ----
        float mx0 = -1e30f, mx1 = -1e30f;
        #pragma unroll
        for (int ni = 0; ni < 8; ni++) {
            mx0 = fmaxf(mx0, fmaxf(sa[ni][0], sa[ni][1]));
            mx1 = fmaxf(mx1, fmaxf(sa[ni][2], sa[ni][3]));
        }
        mx0 = fmaxf(mx0, __shfl_xor_sync(~0u, mx0, 1));
        mx0 = fmaxf(mx0, __shfl_xor_sync(~0u, mx0, 2));
        mx1 = fmaxf(mx1, __shfl_xor_sync(~0u, mx1, 1));
        mx1 = fmaxf(mx1, __shfl_xor_sync(~0u, mx1, 2));
        float mn0 = fmaxf(m0, mx0), mn1 = fmaxf(m1, mx1);
        float al0 = __expf(m0 - mn0), al1 = __expf(m1 - mn1);
        float sum0 = 0.f, sum1 = 0.f;
        #pragma unroll
        for (int ni = 0; ni < 8; ni++) {
            float p00 = __expf(sa[ni][0] - mn0);
            float p01 = __expf(sa[ni][1] - mn0);
            float p10 = __expf(sa[ni][2] - mn1);
            float p11 = __expf(sa[ni][3] - mn1);
            sum0 += p00 + p01; sum1 += p10 + p11;
            QPs[(wm + g) * QSTRW + ni * 4 + c]     = f2bf2(p00, p01);
            QPs[(wm + g + 8) * QSTRW + ni * 4 + c] = f2bf2(p10, p11);
        }
        sum0 += __shfl_xor_sync(~0u, sum0, 1);
        sum0 += __shfl_xor_sync(~0u, sum0, 2);
        sum1 += __shfl_xor_sync(~0u, sum1, 1);
        sum1 += __shfl_xor_sync(~0u, sum1, 2);
        l0 = l0 * al0 + sum0; l1 = l1 * al1 + sum1;
        m0 = mn0; m1 = mn1;
        #pragma unroll
        for (int ni = 0; ni < 8; ni++) {
            oacc[ni][0] *= al0; oacc[ni][1] *= al0;
            oacc[ni][2] *= al1; oacc[ni][3] *= al1;
        }
        __syncthreads();   // all warps done reading Ks; P visible

        // store next K; prefetch next V into regs
        float4 vreg[4];
        if (more) {
            #pragma unroll
            for (int it = 0; it < 4; it++) {
                int d4 = kv_d4b + it * 16;
                Ks[kv_token * KSTRW + (d4 >> 1)]     = f2bf2(kreg[it].x, kreg[it].y);
                Ks[kv_token * KSTRW + (d4 >> 1) + 1] = f2bf2(kreg[it].z, kreg[it].w);
            }
            size_t t = tok0 + (tile + 1) * 64 + kv_token;
            #pragma unroll
            for (int it = 0; it < 4; it++)
                vreg[it] = *(const float4*)&qkv[((t * 3 + 2) * HH + hh) * DH + kv_d4b + it * 16];
        }

        // ---- O += P @ V ----
        #pragma unroll
        for (int kc = 0; kc < 4; kc++) {
            unsigned af[4];
            int bw = kc * 8 + c;
            af[0] = QPs[(wm + g) * QSTRW + bw];
            af[1] = QPs[(wm + g + 8) * QSTRW + bw];
            af[2] = QPs[(wm + g) * QSTRW + bw + 4];
            af[3] = QPs[(wm + g + 8) * QSTRW + bw + 4];
            #pragma unroll
            for (int ni = 0; ni < 8; ni++) {
                int vw = (ni * 8 + g) * KSTRW + kc * 8 + c;
                mma16(oacc[ni], af, Vs[vw], Vs[vw + 4]);
            }
        }
        __syncthreads();   // all warps done reading Vs

        // store next V
        if (more) {
            __nv_bfloat16* Vb = (__nv_bfloat16*)Vs;
            #pragma unroll
            for (int it = 0; it < 4; it++) {
                int d4 = kv_d4b + it * 16;
                Vb[(d4 + 0) * 72 + kv_token] = __float2bfloat16_rn(vreg[it].x);
                Vb[(d4 + 1) * 72 + kv_token] = __float2bfloat16_rn(vreg[it].y);
                Vb[(d4 + 2) * 72 + kv_token] = __float2bfloat16_rn(vreg[it].z);
                Vb[(d4 + 3) * 72 + kv_token] = __float2bfloat16_rn(vreg[it].w);
            }
        }
    }

    // ---- write O ----
    float inv0 = 1.f / l0, inv1 = 1.f / l1;
    size_t t0 = tok0 + q0 + wm + g;
    size_t t1 = t0 + 8;
    #pragma unroll
    for (int ni = 0; ni < 8; ni++) {
        int d = hh * DH + ni * 8 + 2 * c;
        *(float2*)&o[t0 * CC + d] = make_float2(oacc[ni][0] * inv0, oacc[ni][1] * inv0);
        *(float2*)&o[t1 * CC + d] = make_float2(oacc[ni][2] * inv1, oacc[ni][3] * inv1);
    }
}

// ---------------- router ----------------
__global__ __launch_bounds__(256) void route_kernel(
    const float* __restrict__ h2, const float* __restrict__ route_w,
    const float* __restrict__ route_b, const float* __restrict__ rln_g,
    const float* __restrict__ rln_b, const float* __restrict__ noise)
{
    int warp = threadIdx.x >> 5, lane = threadIdx.x & 31;
    int t = blockIdx.x * 8 + warp;
    const float* hrow = h2 + (size_t)t * CC;
    float acc[EE];
    #pragma unroll
    for (int e = 0; e < EE; e++) acc[e] = 0.f;
    for (int c = lane; c < CC; c += 32) {
        float hv = hrow[c];
        const float* rw = route_w + (size_t)c * EE;
        #pragma unroll
        for (int e = 0; e < EE; e++) acc[e] += hv * rw[e];
    }
    #pragma unroll
    for (int e = 0; e < EE; e++)
        #pragma unroll
        for (int off = 16; off > 0; off >>= 1)
            acc[e] += __shfl_xor_sync(~0u, acc[e], off);

    if (lane == 0) {
        float lg[EE];
        float mean = 0.f;
        #pragma unroll
        for (int e = 0; e < EE; e++) { lg[e] = acc[e] + route_b[e]; mean += lg[e]; }
        mean *= (1.f / EE);
        float var = 0.f;
        #pragma unroll
        for (int e = 0; e < EE; e++) { float d = lg[e] - mean; var += d * d; }
        var *= (1.f / EE);
        float rstd = rsqrtf(var + 1e-5f);
        float mx = -1e30f;
        #pragma unroll
        for (int e = 0; e < EE; e++) { lg[e] = (lg[e] - mean) * rstd * rln_g[e] + rln_b[e]; mx = fmaxf(mx, lg[e]); }
        float den = 0.f;
        float r[EE];
        #pragma unroll
        for (int e = 0; e < EE; e++) { r[e] = __expf(lg[e] - mx); den += r[e]; }
        float inv = 1.f / den;
        const float* nrow = noise + (size_t)t * EE;
        #pragma unroll
        for (int e = 0; e < EE; e++) r[e] = r[e] * inv + nrow[e] * 0.125f;

        int i1 = 0;
        #pragma unroll
        for (int e = 1; e < EE; e++) if (r[e] > r[i1]) i1 = e;
        int i2 = (i1 == 0) ? 1 : 0;
        #pragma unroll
        for (int e = 0; e < EE; e++) if (e != i1 && r[e] > r[i2]) i2 = e;

        float vm = fmaxf(r[i1], r[i2]);
        float e1 = __expf(r[i1] - vm), e2 = __expf(r[i2] - vm);
        float wsum = 1.f / (e1 + e2);
        float w1 = e1 * wsum, w2 = e2 * wsum;

        int p1 = atomicAdd(&g_cnt[i1], 1);
        g_list[i1 * TT + p1] = t; g_wt[i1 * TT + p1] = w1;
        int p2 = atomicAdd(&g_cnt[i2], 1);
        g_list[i2 * TT + p2] = t; g_wt[i2 * TT + p2] = w2;
    }
}

__global__ void zero_cnt_kernel() { if (threadIdx.x < EE) g_cnt[threadIdx.x] = 0; }

// ---------------- launch ----------------
extern "C" void kernel_launch(void* const* d_in, const int* in_sizes, int n_in,
                              void* d_out, int out_size)
{
    const float* x       = (const float*)d_in[0];
    const float* noise   = (const float*)d_in[1];
    const float* ln1_g   = (const float*)d_in[2];
    const float* ln1_b   = (const float*)d_in[3];
    const float* qkv_w   = (const float*)d_in[4];
    const float* proj_w  = (const float*)d_in[5];
    const float* proj_b  = (const float*)d_in[6];
    const float* ln2_g   = (const float*)d_in[7];
    const float* ln2_b   = (const float*)d_in[8];
    const float* route_w = (const float*)d_in[9];
    const float* route_b = (const float*)d_in[10];
    const float* rln_g   = (const float*)d_in[11];
    const float* rln_b   = (const float*)d_in[12];
    const float* exp_w   = (const float*)d_in[13];
    const float* exp_b   = (const float*)d_in[14];
    float* out = (float*)d_out;

    float *h1, *qkv, *o, *h2;
    cudaGetSymbolAddress((void**)&h1,  g_h1);
    cudaGetSymbolAddress((void**)&qkv, g_qkv);
    cudaGetSymbolAddress((void**)&o,   g_o);
    cudaGetSymbolAddress((void**)&h2,  g_h2);

    // 1) LN1
    ln_kernel<<<TT, 256>>>(x, ln1_g, ln1_b, h1);
    // 2) QKV GEMM
    tf32_gemm_kernel<false><<<dim3(3 * CC / BN, TT / BM), 256>>>(h1, qkv_w, qkv, 3 * CC, CC, nullptr, nullptr);
    // 3) attention (bf16 tensor cores)
    attn_bf16_kernel<<<dim3(NN / 128, BB * HH), 256>>>(qkv, o);
    // 4) proj + bias + residual -> d_out
    tf32_gemm_kernel<false><<<dim3(CC / BN, TT / BM), 256>>>(o, proj_w, out, CC, CC, proj_b, x);
    // 5) LN2
    ln_kernel<<<TT, 256>>>(out, ln2_g, ln2_b, h2);
    // 6) routing
    zero_cnt_kernel<<<1, 32>>>();
    route_kernel<<<TT / 8, 256>>>(h2, route_w, route_b, rln_g, rln_b, noise);
    // 7) MoE grouped GEMM, accumulates into d_out
    tf32_gemm_kernel<true><<<dim3(CC / BN, TT / BM, EE), 256>>>(h2, exp_w, out, CC, CC, exp_b, nullptr);
}

// round 7
// speedup vs baseline: 2.9656x; 1.0734x over previous
#include <cuda_runtime.h>
#include <cuda_bf16.h>
#include <math.h>

#define BB 16
#define NN 1024
#define CC 768
#define HH 12
#define DH 64
#define EE 8
#define TT (BB*NN)

// ---------------- scratch (no allocations allowed) ----------------
__device__ float g_h1[(size_t)TT * CC];              // LN1 output
__device__ __nv_bfloat16 g_qb[(size_t)TT * CC];      // Q  [b][h][n][d]  (pre-scaled)
__device__ __nv_bfloat16 g_kb[(size_t)TT * CC];      // K  [b][h][n][d]
__device__ __nv_bfloat16 g_vt[(size_t)TT * CC];      // V  [b][h][d][n]  (transposed)
__device__ float g_o[(size_t)TT * CC];               // attention output
__device__ float g_h2[(size_t)TT * CC];              // LN2 output
__device__ int   g_cnt[EE];
__device__ int   g_list[EE * TT];
__device__ float g_wt[EE * TT];

__device__ __forceinline__ unsigned f2tf(float f) {
    unsigned u; asm("cvt.rna.tf32.f32 %0, %1;" : "=r"(u) : "f"(f)); return u;
}
__device__ __forceinline__ unsigned f2bf2(float lo, float hi) {
    __nv_bfloat162 h = __floats2bfloat162_rn(lo, hi);
    return *reinterpret_cast<unsigned*>(&h);
}
__device__ __forceinline__ void mma8(float* c, const unsigned* a, const unsigned* b) {
    asm volatile("mma.sync.aligned.m16n8k8.row.col.f32.tf32.tf32.f32 "
        "{%0,%1,%2,%3}, {%4,%5,%6,%7}, {%8,%9}, {%0,%1,%2,%3};"
        : "+f"(c[0]), "+f"(c[1]), "+f"(c[2]), "+f"(c[3])
        : "r"(a[0]), "r"(a[1]), "r"(a[2]), "r"(a[3]), "r"(b[0]), "r"(b[1]));
}
__device__ __forceinline__ void mma16(float* c, const unsigned* a, unsigned b0, unsigned b1) {
    asm volatile("mma.sync.aligned.m16n8k16.row.col.f32.bf16.bf16.f32 "
        "{%0,%1,%2,%3}, {%4,%5,%6,%7}, {%8,%9}, {%0,%1,%2,%3};"
        : "+f"(c[0]), "+f"(c[1]), "+f"(c[2]), "+f"(c[3])
        : "r"(a[0]), "r"(a[1]), "r"(a[2]), "r"(a[3]), "r"(b0), "r"(b1));
}

// ---------------- LayerNorm ----------------
__global__ __launch_bounds__(256) void ln_kernel(const float* __restrict__ in,
    const float* __restrict__ gamma, const float* __restrict__ beta,
    float* __restrict__ out)
{
    int t = blockIdx.x;
    const float* row = in + (size_t)t * CC;
    float s = 0.f, s2 = 0.f;
    for (int i = threadIdx.x; i < CC; i += 256) { float v = row[i]; s += v; s2 += v * v; }
    __shared__ float sh[64];
    #pragma unroll
    for (int o = 16; o > 0; o >>= 1) { s += __shfl_xor_sync(~0u, s, o); s2 += __shfl_xor_sync(~0u, s2, o); }
    int w = threadIdx.x >> 5, l = threadIdx.x & 31;
    if (l == 0) { sh[w] = s; sh[32 + w] = s2; }
    __syncthreads();
    if (threadIdx.x == 0) {
        float a = 0.f, b = 0.f;
        #pragma unroll
        for (int i = 0; i < 8; i++) { a += sh[i]; b += sh[32 + i]; }
        sh[0] = a; sh[1] = b;
    }
    __syncthreads();
    float mean = sh[0] * (1.f / CC);
    float var  = sh[1] * (1.f / CC) - mean * mean;
    float rstd = rsqrtf(var + 1e-5f);
    float* orow = out + (size_t)t * CC;
    for (int i = threadIdx.x; i < CC; i += 256)
        orow[i] = (row[i] - mean) * rstd * gamma[i] + beta[i];
}

// ---------------- TF32 tensor-core GEMM 128x128x16 ----------------
// MODE 0: C = A@B [+bias][+resid]    MODE 1: MoE gather/scatter    MODE 2: QKV -> bf16 q/k/vt
#define BM 128
#define BN 128
#define BK 16
#define ASTR (BM + 8)
#define BSTR (BN + 8)

template<int MODE>
__global__ __launch_bounds__(256, 2) void tf32_gemm_kernel(
    const float* __restrict__ A, const float* __restrict__ Bm, float* __restrict__ Cm,
    int Nn, int K,
    const float* __restrict__ bias, const float* __restrict__ resid,
    __nv_bfloat16* __restrict__ qb, __nv_bfloat16* __restrict__ kb,
    __nv_bfloat16* __restrict__ vtb)
{
    __shared__ unsigned As[2][BK][ASTR];
    __shared__ unsigned Bs[2][BK][BSTR];
    __shared__ int   stok[BM];
    __shared__ float swt[BM];

    int bm = blockIdx.y * BM, bn = blockIdx.x * BN;
    int tid = threadIdx.x;
    int e = 0;
    if (MODE == 1) {
        e = blockIdx.z;
        int cnt = g_cnt[e];
        if (bm >= cnt) return;
        if (tid < BM) {
            int m = bm + tid;
            if (m < cnt) { stok[tid] = g_list[e * TT + m]; swt[tid] = g_wt[e * TT + m]; }
            else         { stok[tid] = -1; swt[tid] = 0.f; }
        }
        __syncthreads();
    }

    int lrowA = tid & 127;
    int kcolA = (tid >> 7) * 8;
    const float* Aptr;
    if (MODE == 1) {
        int tok = stok[lrowA];
        Aptr = (tok >= 0) ? A + (size_t)tok * K + kcolA : nullptr;
    } else {
        Aptr = A + (size_t)(bm + lrowA) * K + kcolA;
    }
    int rowB = tid >> 5;
    int colB = (tid & 31) << 2;
    const float* Bbase = (MODE == 1) ? (Bm + (size_t)e * K * Nn) : Bm;
    const float* Bptr = Bbase + (size_t)rowB * Nn + bn + colB;

    float4 pa0, pa1, pb0, pb1;
    const float4 z4 = make_float4(0.f, 0.f, 0.f, 0.f);

    pa0 = Aptr ? *(const float4*)(Aptr + 0) : z4;
    pa1 = Aptr ? *(const float4*)(Aptr + 4) : z4;
    pb0 = *(const float4*)(Bptr);
    pb1 = *(const float4*)(Bptr + (size_t)8 * Nn);

    {
        As[0][kcolA + 0][lrowA] = f2tf(pa0.x); As[0][kcolA + 1][lrowA] = f2tf(pa0.y);
        As[0][kcolA + 2][lrowA] = f2tf(pa0.z); As[0][kcolA + 3][lrowA] = f2tf(pa0.w);
        As[0][kcolA + 4][lrowA] = f2tf(pa1.x); As[0][kcolA + 5][lrowA] = f2tf(pa1.y);
        As[0][kcolA + 6][lrowA] = f2tf(pa1.z); As[0][kcolA + 7][lrowA] = f2tf(pa1.w);
        uint4 u0 = make_uint4(f2tf(pb0.x), f2tf(pb0.y), f2tf(pb0.z), f2tf(pb0.w));
        uint4 u1 = make_uint4(f2tf(pb1.x), f2tf(pb1.y), f2tf(pb1.z), f2tf(pb1.w));
        *(uint4*)&Bs[0][rowB][colB] = u0;
        *(uint4*)&Bs[0][rowB + 8][colB] = u1;
    }
    __syncthreads();

    int lane = tid & 31, wid = tid >> 5;
    int wm = (wid & 3) * 32;
    int wn = (wid >> 2) * 64;
    int g = lane >> 2, c = lane & 3;

    float acc[2][8][4];
    #pragma unroll
    for (int mi = 0; mi < 2; mi++)
        #pragma unroll
        for (int ni = 0; ni < 8; ni++)
            #pragma unroll
            for (int q = 0; q < 4; q++) acc[mi][ni][q] = 0.f;

    int nIter = K / BK;
    for (int it = 0; it < nIter; it++) {
        int cur = it & 1, nxt = cur ^ 1;
        int k0n = (it + 1) * BK;
        if (it + 1 < nIter) {
            pa0 = Aptr ? *(const float4*)(Aptr + k0n) : z4;
            pa1 = Aptr ? *(const float4*)(Aptr + k0n + 4) : z4;
            pb0 = *(const float4*)(Bptr + (size_t)k0n * Nn);
            pb1 = *(const float4*)(Bptr + (size_t)(k0n + 8) * Nn);
        }

        #pragma unroll
        for (int kk = 0; kk < BK; kk += 8) {
            unsigned af[2][4];
            #pragma unroll
            for (int mi = 0; mi < 2; mi++) {
                af[mi][0] = As[cur][kk + c][wm + mi * 16 + g];
                af[mi][1] = As[cur][kk + c][wm + mi * 16 + g + 8];
                af[mi][2] = As[cur][kk + c + 4][wm + mi * 16 + g];
                af[mi][3] = As[cur][kk + c + 4][wm + mi * 16 + g + 8];
            }
            #pragma unroll
            for (int ni = 0; ni < 8; ni++) {
                unsigned bf[2];
                bf[0] = Bs[cur][kk + c][wn + ni * 8 + g];
                bf[1] = Bs[cur][kk + c + 4][wn + ni * 8 + g];
                mma8(acc[0][ni], af[0], bf);
                mma8(acc[1][ni], af[1], bf);
            }
        }

        if (it + 1 < nIter) {
            As[nxt][kcolA + 0][lrowA] = f2tf(pa0.x); As[nxt][kcolA + 1][lrowA] = f2tf(pa0.y);
            As[nxt][kcolA + 2][lrowA] = f2tf(pa0.z); As[nxt][kcolA + 3][lrowA] = f2tf(pa0.w);
            As[nxt][kcolA + 4][lrowA] = f2tf(pa1.x); As[nxt][kcolA + 5][lrowA] = f2tf(pa1.y);
            As[nxt][kcolA + 6][lrowA] = f2tf(pa1.z); As[nxt][kcolA + 7][lrowA] = f2tf(pa1.w);
            uint4 u0 = make_uint4(f2tf(pb0.x), f2tf(pb0.y), f2tf(pb0.z), f2tf(pb0.w));
            uint4 u1 = make_uint4(f2tf(pb1.x), f2tf(pb1.y), f2tf(pb1.z), f2tf(pb1.w));
            *(uint4*)&Bs[nxt][rowB][colB] = u0;
            *(uint4*)&Bs[nxt][rowB + 8][colB] = u1;
        }
        __syncthreads();
    }

    // epilogue
    #pragma unroll
    for (int mi = 0; mi < 2; mi++) {
        int rl0 = wm + mi * 16 + g;
        int rl1 = rl0 + 8;
        if (MODE == 1) {
            int tk0 = stok[rl0], tk1 = stok[rl1];
            float w0 = swt[rl0], w1 = swt[rl1];
            #pragma unroll
            for (int ni = 0; ni < 8; ni++) {
                int cn = bn + wn + ni * 8 + 2 * c;
                float b0 = bias[(size_t)e * Nn + cn], b1 = bias[(size_t)e * Nn + cn + 1];
                if (tk0 >= 0) {
                    float* p = Cm + (size_t)tk0 * Nn + cn;
                    atomicAdd(p,     w0 * (acc[mi][ni][0] + b0));
                    atomicAdd(p + 1, w0 * (acc[mi][ni][1] + b1));
                }
                if (tk1 >= 0) {
                    float* p = Cm + (size_t)tk1 * Nn + cn;
                    atomicAdd(p,     w1 * (acc[mi][ni][2] + b0));
                    atomicAdd(p + 1, w1 * (acc[mi][ni][3] + b1));
                }
            }
        } else if (MODE == 2) {
            int r0 = bm + rl0, r1 = bm + rl1;
            int b0r = r0 >> 10, n0 = r0 & 1023;
            int b1r = r1 >> 10, n1 = r1 & 1023;
            #pragma unroll
            for (int ni = 0; ni < 8; ni++) {
                int cn = bn + wn + ni * 8 + 2 * c;
                int sect = cn / CC;          // 0=Q 1=K 2=V (uniform per block)
                int cc = cn - sect * CC;
                int h = cc >> 6, d = cc & 63;
                if (sect == 0) {
                    size_t i0 = ((size_t)(b0r * HH + h) * NN + n0) * DH + d;
                    size_t i1 = ((size_t)(b1r * HH + h) * NN + n1) * DH + d;
                    *(unsigned*)&qb[i0] = f2bf2(acc[mi][ni][0] * 0.125f, acc[mi][ni][1] * 0.125f);
                    *(unsigned*)&qb[i1] = f2bf2(acc[mi][ni][2] * 0.125f, acc[mi][ni][3] * 0.125f);
                } else if (sect == 1) {
                    size_t i0 = ((size_t)(b0r * HH + h) * NN + n0) * DH + d;
                    size_t i1 = ((size_t)(b1r * HH + h) * NN + n1) * DH + d;
                    *(unsigned*)&kb[i0] = f2bf2(acc[mi][ni][0], acc[mi][ni][1]);
                    *(unsigned*)&kb[i1] = f2bf2(acc[mi][ni][2], acc[mi][ni][3]);
                } else {
                    size_t base0 = (size_t)(b0r * HH + h) * DH;
                    size_t base1 = (size_t)(b1r * HH + h) * DH;
                    vtb[(base0 + d) * NN + n0]     = __float2bfloat16_rn(acc[mi][ni][0]);
                    vtb[(base0 + d + 1) * NN + n0] = __float2bfloat16_rn(acc[mi][ni][1]);
                    vtb[(base1 + d) * NN + n1]     = __float2bfloat16_rn(acc[mi][ni][2]);
                    vtb[(base1 + d + 1) * NN + n1] = __float2bfloat16_rn(acc[mi][ni][3]);
                }
            }
        } else {
            int r0 = bm + rl0, r1 = bm + rl1;
            #pragma unroll
            for (int ni = 0; ni < 8; ni++) {
                int cn = bn + wn + ni * 8 + 2 * c;
                float2 v0 = make_float2(acc[mi][ni][0], acc[mi][ni][1]);
                float2 v1 = make_float2(acc[mi][ni][2], acc[mi][ni][3]);
                if (bias) {
                    float b0 = bias[cn], b1 = bias[cn + 1];
                    v0.x += b0; v0.y += b1; v1.x += b0; v1.y += b1;
                }
                if (resid) {
                    float2 r0v = *(const float2*)(resid + (size_t)r0 * Nn + cn);
                    float2 r1v = *(const float2*)(resid + (size_t)r1 * Nn + cn);
                    v0.x += r0v.x; v0.y += r0v.y; v1.x += r1v.x; v1.y += r1v.y;
                }
                *(float2*)(Cm + (size_t)r0 * Nn + cn) = v0;
                *(float2*)(Cm + (size_t)r1 * Nn + cn) = v1;
            }
        }
    }
}

// ---------------- bf16 flash attention, contiguous operands ----------------
// grid (NN/128, BB*HH); 256 threads (8 warps x 16 q-rows); 2 CTAs/SM
#define QSTRW 36
#define KSTRW 36
#define ATTN_SMEM ((128*QSTRW + 2*64*KSTRW + 2*64*KSTRW) * 4)

__global__ __launch_bounds__(256, 2) void attn_bf16_kernel(
    const __nv_bfloat16* __restrict__ qb,
    const __nv_bfloat16* __restrict__ kb,
    const __nv_bfloat16* __restrict__ vt,
    float* __restrict__ o)
{
    extern __shared__ unsigned smem_u[];
    unsigned* QPs = smem_u;                       // 128 x 36
    unsigned* Ks  = QPs + 128 * QSTRW;            // 2 x 64 x 36
    unsigned* Vs  = Ks + 2 * 64 * KSTRW;          // 2 x 64 x 36

    int bh = blockIdx.y;
    int bb = bh / HH, hh = bh % HH;
    int q0 = blockIdx.x * 128;
    int tid = threadIdx.x;
    int lane = tid & 31, wid = tid >> 5;
    int wm = wid * 16;
    int g = lane >> 2, c = lane & 3;

    const __nv_bfloat16* q_head = qb + ((size_t)(bb * HH + hh) * NN + q0) * DH;
    const __nv_bfloat16* k_head = kb + (size_t)(bb * HH + hh) * NN * DH;
    const __nv_bfloat16* v_head = vt + (size_t)(bb * HH + hh) * DH * NN;

    // ---- stage Q (already scaled): 128 rows x 64 bf16, contiguous ----
    {
        int row = tid >> 1, seg = tid & 1;
        const uint4* src = (const uint4*)(q_head + (size_t)row * DH + seg * 32);
        unsigned* dst = QPs + row * QSTRW + seg * 16;
        #pragma unroll
        for (int i = 0; i < 4; i++)
            *(uint4*)(dst + i * 4) = src[i];
    }
    __syncthreads();

    // ---- Q fragments ----
    unsigned qf[4][4];
    #pragma unroll
    for (int kc = 0; kc < 4; kc++) {
        int bw = kc * 8 + c;
        qf[kc][0] = QPs[(wm + g) * QSTRW + bw];
        qf[kc][1] = QPs[(wm + g + 8) * QSTRW + bw];
        qf[kc][2] = QPs[(wm + g) * QSTRW + bw + 4];
        qf[kc][3] = QPs[(wm + g + 8) * QSTRW + bw + 4];
    }
    __syncthreads();   // QPs free for P

    float oacc[8][4];
    #pragma unroll
    for (int ni = 0; ni < 8; ni++)
        #pragma unroll
        for (int q = 0; q < 4; q++) oacc[ni][q] = 0.f;
    float m0 = -1e30f, m1 = -1e30f, l0 = 0.f, l1 = 0.f;

    // per-thread fill coords: token/d row (tid&63), segment pair {seg, seg+4} of 8 bf16 each
    int ktok = tid & 63, kseg = tid >> 6;
    int vd = tid & 63, vseg = tid >> 6;

    // ---- prime tile 0 into buffer 0 ----
    {
        const uint4* ksrc = (const uint4*)(k_head + (size_t)ktok * DH);
        *(uint4*)(Ks + ktok * KSTRW + kseg * 4) = ksrc[kseg];
        *(uint4*)(Ks + ktok * KSTRW + (kseg + 4) * 4) = ksrc[kseg + 4];
        const __nv_bfloat16* vrow = v_head + (size_t)vd * NN;
        *(uint4*)(Vs + vd * KSTRW + vseg * 4)       = *(const uint4*)(vrow + vseg * 8);
        *(uint4*)(Vs + vd * KSTRW + (vseg + 4) * 4) = *(const uint4*)(vrow + (vseg + 4) * 8);
    }
    __syncthreads();

    const int NTILES = NN / 64;
    for (int tile = 0; tile < NTILES; tile++) {
        int cur = tile & 1, nxt = cur ^ 1;
        const unsigned* Kb = Ks + cur * 64 * KSTRW;
        const unsigned* Vb = Vs + cur * 64 * KSTRW;
        bool more = (tile + 1 < NTILES);

        // prefetch next tile into regs
        uint4 kx0, kx1, vx0, vx1;
        if (more) {
            const uint4* ksrc = (const uint4*)(k_head + (size_t)(tile + 1) * 64 * DH + (size_t)ktok * DH);
            kx0 = ksrc[kseg]; kx1 = ksrc[kseg + 4];
            const __nv_bfloat16* vrow = v_head + (size_t)vd * NN + (tile + 1) * 64;
            vx0 = *(const uint4*)(vrow + vseg * 8);
            vx1 = *(const uint4*)(vrow + (vseg + 4) * 8);
        }

        // ---- S = Q @ K^T ----
        float sa[8][4];
        #pragma unroll
        for (int ni = 0; ni < 8; ni++)
            #pragma unroll
            for (int q = 0; q < 4; q++) sa[ni][q] = 0.f;
        #pragma unroll
        for (int kc = 0; kc < 4; kc++) {
            #pragma unroll
            for (int ni = 0; ni < 8; ni++) {
                int bw = (ni * 8 + g) * KSTRW + kc * 8 + c;
                mma16(sa[ni], qf[kc], Kb[bw], Kb[bw + 4]);
            }
        }

        // ---- online softmax + bf16 P store (warp-local rows) ----
        float mx0 = -1e30f, mx1 = -1e30f;
        #pragma unroll
        for (int ni = 0; ni < 8; ni++) {
            mx0 = fmaxf(mx0, fmaxf(sa[ni][0], sa[ni][1]));
            mx1 = fmaxf(mx1, fmaxf(sa[ni][2], sa[ni][3]));
        }
        mx0 = fmaxf(mx0, __shfl_xor_sync(~0u, mx0, 1));
        mx0 = fmaxf(mx0, __shfl_xor_sync(~0u, mx0, 2));
        mx1 = fmaxf(mx1, __shfl_xor_sync(~0u, mx1, 1));
        mx1 = fmaxf(mx1, __shfl_xor_sync(~0u, mx1, 2));
        float mn0 = fmaxf(m0, mx0), mn1 = fmaxf(m1, mx1);
        float al0 = __expf(m0 - mn0), al1 = __expf(m1 - mn1);
        float sum0 = 0.f, sum1 = 0.f;
        #pragma unroll
        for (int ni = 0; ni < 8; ni++) {
            float p00 = __expf(sa[ni][0] - mn0);
            float p01 = __expf(sa[ni][1] - mn0);
            float p10 = __expf(sa[ni][2] - mn1);
            float p11 = __expf(sa[ni][3] - mn1);
            sum0 += p00 + p01; sum1 += p10 + p11;
            QPs[(wm + g) * QSTRW + ni * 4 + c]     = f2bf2(p00, p01);
            QPs[(wm + g + 8) * QSTRW + ni * 4 + c] = f2bf2(p10, p11);
        }
        sum0 += __shfl_xor_sync(~0u, sum0, 1);
        sum0 += __shfl_xor_sync(~0u, sum0, 2);
        sum1 += __shfl_xor_sync(~0u, sum1, 1);
        sum1 += __shfl_xor_sync(~0u, sum1, 2);
        l0 = l0 * al0 + sum0; l1 = l1 * al1 + sum1;
        m0 = mn0; m1 = mn1;
        #pragma unroll
        for (int ni = 0; ni < 8; ni++) {
            oacc[ni][0] *= al0; oacc[ni][1] *= al0;
            oacc[ni][2] *= al1; oacc[ni][3] *= al1;
        }
        __syncwarp();   // P rows are warp-private

        // store next K into other buffer (drained at last tile's barrier)
        if (more) {
            unsigned* Kn = Ks + nxt * 64 * KSTRW;
            *(uint4*)(Kn + ktok * KSTRW + kseg * 4) = kx0;
            *(uint4*)(Kn + ktok * KSTRW + (kseg + 4) * 4) = kx1;
        }

        // ---- O += P @ V ----
        #pragma unroll
        for (int kc = 0; kc < 4; kc++) {
            unsigned af[4];
            int bw = kc * 8 + c;
            af[0] = QPs[(wm + g) * QSTRW + bw];
            af[1] = QPs[(wm + g + 8) * QSTRW + bw];
            af[2] = QPs[(wm + g) * QSTRW + bw + 4];
            af[3] = QPs[(wm + g + 8) * QSTRW + bw + 4];
            #pragma unroll
            for (int ni = 0; ni < 8; ni++) {
                int vw = (ni * 8 + g) * KSTRW + kc * 8 + c;
                mma16(oacc[ni], af, Vb[vw], Vb[vw + 4]);
            }
        }

        // store next V
        if (more) {
            unsigned* Vn = Vs + nxt * 64 * KSTRW;
            *(uint4*)(Vn + vd * KSTRW + vseg * 4) = vx0;
            *(uint4*)(Vn + vd * KSTRW + (vseg + 4) * 4) = vx1;
        }
        __syncthreads();   // one barrier per tile
    }

    // ---- write O ----
    float inv0 = 1.f / l0, inv1 = 1.f / l1;
    size_t t0 = (size_t)bb * NN + q0 + wm + g;
    size_t t1 = t0 + 8;
    #pragma unroll
    for (int ni = 0; ni < 8; ni++) {
        int d = hh * DH + ni * 8 + 2 * c;
        *(float2*)&o[t0 * CC + d] = make_float2(oacc[ni][0] * inv0, oacc[ni][1] * inv0);
        *(float2*)&o[t1 * CC + d] = make_float2(oacc[ni][2] * inv1, oacc[ni][3] * inv1);
    }
}

// ---------------- router ----------------
__global__ __launch_bounds__(256) void route_kernel(
    const float* __restrict__ h2, const float* __restrict__ route_w,
    const float* __restrict__ route_b, const float* __restrict__ rln_g,
    const float* __restrict__ rln_b, const float* __restrict__ noise)
{
    int warp = threadIdx.x >> 5, lane = threadIdx.x & 31;
    int t = blockIdx.x * 8 + warp;
    const float* hrow = h2 + (size_t)t * CC;
    float acc[EE];
    #pragma unroll
    for (int e = 0; e < EE; e++) acc[e] = 0.f;
    for (int c = lane; c < CC; c += 32) {
        float hv = hrow[c];
        const float* rw = route_w + (size_t)c * EE;
        #pragma unroll
        for (int e = 0; e < EE; e++) acc[e] += hv * rw[e];
    }
    #pragma unroll
    for (int e = 0; e < EE; e++)
        #pragma unroll
        for (int off = 16; off > 0; off >>= 1)
            acc[e] += __shfl_xor_sync(~0u, acc[e], off);

    if (lane == 0) {
        float lg[EE];
        float mean = 0.f;
        #pragma unroll
        for (int e = 0; e < EE; e++) { lg[e] = acc[e] + route_b[e]; mean += lg[e]; }
        mean *= (1.f / EE);
        float var = 0.f;
        #pragma unroll
        for (int e = 0; e < EE; e++) { float d = lg[e] - mean; var += d * d; }
        var *= (1.f / EE);
        float rstd = rsqrtf(var + 1e-5f);
        float mx = -1e30f;
        #pragma unroll
        for (int e = 0; e < EE; e++) { lg[e] = (lg[e] - mean) * rstd * rln_g[e] + rln_b[e]; mx = fmaxf(mx, lg[e]); }
        float den = 0.f;
        float r[EE];
        #pragma unroll
        for (int e = 0; e < EE; e++) { r[e] = __expf(lg[e] - mx); den += r[e]; }
        float inv = 1.f / den;
        const float* nrow = noise + (size_t)t * EE;
        #pragma unroll
        for (int e = 0; e < EE; e++) r[e] = r[e] * inv + nrow[e] * 0.125f;

        int i1 = 0;
        #pragma unroll
        for (int e = 1; e < EE; e++) if (r[e] > r[i1]) i1 = e;
        int i2 = (i1 == 0) ? 1 : 0;
        #pragma unroll
        for (int e = 0; e < EE; e++) if (e != i1 && r[e] > r[i2]) i2 = e;

        float vm = fmaxf(r[i1], r[i2]);
        float e1 = __expf(r[i1] - vm), e2 = __expf(r[i2] - vm);
        float wsum = 1.f / (e1 + e2);
        float w1 = e1 * wsum, w2 = e2 * wsum;

        int p1 = atomicAdd(&g_cnt[i1], 1);
        g_list[i1 * TT + p1] = t; g_wt[i1 * TT + p1] = w1;
        int p2 = atomicAdd(&g_cnt[i2], 1);
        g_list[i2 * TT + p2] = t; g_wt[i2 * TT + p2] = w2;
    }
}

__global__ void zero_cnt_kernel() { if (threadIdx.x < EE) g_cnt[threadIdx.x] = 0; }

// ---------------- launch ----------------
extern "C" void kernel_launch(void* const* d_in, const int* in_sizes, int n_in,
                              void* d_out, int out_size)
{
    const float* x       = (const float*)d_in[0];
    const float* noise   = (const float*)d_in[1];
    const float* ln1_g   = (const float*)d_in[2];
    const float* ln1_b   = (const float*)d_in[3];
    const float* qkv_w   = (const float*)d_in[4];
    const float* proj_w  = (const float*)d_in[5];
    const float* proj_b  = (const float*)d_in[6];
    const float* ln2_g   = (const float*)d_in[7];
    const float* ln2_b   = (const float*)d_in[8];
    const float* route_w = (const float*)d_in[9];
    const float* route_b = (const float*)d_in[10];
    const float* rln_g   = (const float*)d_in[11];
    const float* rln_b   = (const float*)d_in[12];
    const float* exp_w   = (const float*)d_in[13];
    const float* exp_b   = (const float*)d_in[14];
    float* out = (float*)d_out;

    float *h1, *o, *h2;
    __nv_bfloat16 *qbp, *kbp, *vtp;
    cudaGetSymbolAddress((void**)&h1,  g_h1);
    cudaGetSymbolAddress((void**)&o,   g_o);
    cudaGetSymbolAddress((void**)&h2,  g_h2);
    cudaGetSymbolAddress((void**)&qbp, g_qb);
    cudaGetSymbolAddress((void**)&kbp, g_kb);
    cudaGetSymbolAddress((void**)&vtp, g_vt);

    cudaFuncSetAttribute(attn_bf16_kernel, cudaFuncAttributeMaxDynamicSharedMemorySize, (int)ATTN_SMEM);

    // 1) LN1
    ln_kernel<<<TT, 256>>>(x, ln1_g, ln1_b, h1);
    // 2) QKV GEMM -> bf16 q/k/vt (attention-native layouts)
    tf32_gemm_kernel<2><<<dim3(3 * CC / BN, TT / BM), 256>>>(h1, qkv_w, nullptr, 3 * CC, CC, nullptr, nullptr, qbp, kbp, vtp);
    // 3) attention (bf16 tensor cores, contiguous operands)
    attn_bf16_kernel<<<dim3(NN / 128, BB * HH), 256, ATTN_SMEM>>>(qbp, kbp, vtp, o);
    // 4) proj + bias + residual -> d_out
    tf32_gemm_kernel<0><<<dim3(CC / BN, TT / BM), 256>>>(o, proj_w, out, CC, CC, proj_b, x, nullptr, nullptr, nullptr);
    // 5) LN2
    ln_kernel<<<TT, 256>>>(out, ln2_g, ln2_b, h2);
    // 6) routing
    zero_cnt_kernel<<<1, 32>>>();
    route_kernel<<<TT / 8, 256>>>(h2, route_w, route_b, rln_g, rln_b, noise);
    // 7) MoE grouped GEMM, accumulates into d_out
    tf32_gemm_kernel<1><<<dim3(CC / BN, TT / BM, EE), 256>>>(h2, exp_w, out, CC, CC, exp_b, nullptr, nullptr, nullptr, nullptr);
}

// round 8
// speedup vs baseline: 3.7932x; 1.2791x over previous
#include <cuda_runtime.h>
#include <cuda_bf16.h>
#include <math.h>

#define BB 16
#define NN 1024
#define CC 768
#define HH 12
#define DH 64
#define EE 8
#define TT (BB*NN)

// ---------------- scratch (no allocations allowed) ----------------
__device__ float g_h1[(size_t)TT * CC];              // LN1 output (tf32-rounded)
__device__ __nv_bfloat16 g_qb[(size_t)TT * CC];      // Q  [b][h][n][d]  (pre-scaled)
__device__ __nv_bfloat16 g_kb[(size_t)TT * CC];      // K  [b][h][n][d]
__device__ __nv_bfloat16 g_vt[(size_t)TT * CC];      // V  [b][h][d][n]  (transposed)
__device__ float g_o[(size_t)TT * CC];               // attention output (tf32-rounded)
__device__ float g_h2[(size_t)TT * CC];              // LN2 output (full, for router)
__device__ float g_h2r[(size_t)TT * CC];             // LN2 output (tf32-rounded, MoE A)
__device__ float g_qkvwr[(size_t)CC * 3 * CC];       // tf32-rounded weights
__device__ float g_projwr[(size_t)CC * CC];
__device__ float g_expwr[(size_t)EE * CC * CC];
__device__ int   g_cnt[EE];
__device__ int   g_list[EE * TT];
__device__ float g_wt[EE * TT];

__device__ __forceinline__ unsigned f2tf(float f) {
    unsigned u; asm("cvt.rna.tf32.f32 %0, %1;" : "=r"(u) : "f"(f)); return u;
}
__device__ __forceinline__ float tfround(float f) { return __uint_as_float(f2tf(f)); }
__device__ __forceinline__ unsigned f2bf2(float lo, float hi) {
    __nv_bfloat162 h = __floats2bfloat162_rn(lo, hi);
    return *reinterpret_cast<unsigned*>(&h);
}
__device__ __forceinline__ void mma8(float* c, const unsigned* a, const unsigned* b) {
    asm volatile("mma.sync.aligned.m16n8k8.row.col.f32.tf32.tf32.f32 "
        "{%0,%1,%2,%3}, {%4,%5,%6,%7}, {%8,%9}, {%0,%1,%2,%3};"
        : "+f"(c[0]), "+f"(c[1]), "+f"(c[2]), "+f"(c[3])
        : "r"(a[0]), "r"(a[1]), "r"(a[2]), "r"(a[3]), "r"(b[0]), "r"(b[1]));
}
__device__ __forceinline__ void mma16(float* c, const unsigned* a, unsigned b0, unsigned b1) {
    asm volatile("mma.sync.aligned.m16n8k16.row.col.f32.bf16.bf16.f32 "
        "{%0,%1,%2,%3}, {%4,%5,%6,%7}, {%8,%9}, {%0,%1,%2,%3};"
        : "+f"(c[0]), "+f"(c[1]), "+f"(c[2]), "+f"(c[3])
        : "r"(a[0]), "r"(a[1]), "r"(a[2]), "r"(a[3]), "r"(b0), "r"(b1));
}
__device__ __forceinline__ void cp16(unsigned dst, const void* src, int sz) {
    asm volatile("cp.async.cg.shared.global [%0], [%1], 16, %2;"
        :: "r"(dst), "l"(src), "r"(sz) : "memory");
}

// ---------------- weight tf32 pre-round ----------------
__global__ __launch_bounds__(256) void round_kernel(const float* __restrict__ in,
                                                    float* __restrict__ out, int n)
{
    int i = blockIdx.x * 256 + threadIdx.x;
    if (i < n) out[i] = tfround(in[i]);
}

// ---------------- LayerNorm (optional full + tf32-rounded outputs) ----------------
__global__ __launch_bounds__(256) void ln_kernel(const float* __restrict__ in,
    const float* __restrict__ gamma, const float* __restrict__ beta,
    float* __restrict__ out, float* __restrict__ outr)
{
    int t = blockIdx.x;
    const float* row = in + (size_t)t * CC;
    float s = 0.f, s2 = 0.f;
    for (int i = threadIdx.x; i < CC; i += 256) { float v = row[i]; s += v; s2 += v * v; }
    __shared__ float sh[64];
    #pragma unroll
    for (int o = 16; o > 0; o >>= 1) { s += __shfl_xor_sync(~0u, s, o); s2 += __shfl_xor_sync(~0u, s2, o); }
    int w = threadIdx.x >> 5, l = threadIdx.x & 31;
    if (l == 0) { sh[w] = s; sh[32 + w] = s2; }
    __syncthreads();
    if (threadIdx.x == 0) {
        float a = 0.f, b = 0.f;
        #pragma unroll
        for (int i = 0; i < 8; i++) { a += sh[i]; b += sh[32 + i]; }
        sh[0] = a; sh[1] = b;
    }
    __syncthreads();
    float mean = sh[0] * (1.f / CC);
    float var  = sh[1] * (1.f / CC) - mean * mean;
    float rstd = rsqrtf(var + 1e-5f);
    for (int i = threadIdx.x; i < CC; i += 256) {
        float v = (row[i] - mean) * rstd * gamma[i] + beta[i];
        if (out)  out[(size_t)t * CC + i] = v;
        if (outr) outr[(size_t)t * CC + i] = tfround(v);
    }
}

// ---------------- TF32 GEMM, 4-stage cp.async pipeline, 128x128x16 ----------------
// Operands must be tf32-pre-rounded fp32 (mma truncation is then exact).
// MODE 0: C=A@B [+bias][+resid]   MODE 1: MoE gather/scatter   MODE 2: QKV -> bf16 q/k/vt
#define BM 128
#define BN 128
#define GBK 16
#define GS 4
#define AW 20     // A row stride (words): 16 data + 4 pad -> conflict-free frag LDS
#define BWW 136   // B row stride (words): 128 data + 8 pad
#define GEMM_SMEM ((GS*BM*AW + GS*GBK*BWW + 256) * 4)

template<int MODE>
__global__ __launch_bounds__(256, 2) void tf32_gemm_kernel(
    const float* __restrict__ A, const float* __restrict__ Bm, float* __restrict__ Cm,
    int Nn, int K,
    const float* __restrict__ bias, const float* __restrict__ resid,
    __nv_bfloat16* __restrict__ qb, __nv_bfloat16* __restrict__ kb,
    __nv_bfloat16* __restrict__ vtb)
{
    extern __shared__ float gsm[];
    float* As = gsm;                               // GS x 128 x AW
    float* Bs = As + GS * BM * AW;                 // GS x 16 x BWW
    int*   stok = (int*)(Bs + GS * GBK * BWW);     // 128
    float* swt  = (float*)(stok + BM);             // 128

    int bm = blockIdx.y * BM, bn = blockIdx.x * BN;
    int tid = threadIdx.x;
    int e = 0;
    if (MODE == 1) {
        e = blockIdx.z;
        int cnt = g_cnt[e];
        if (bm >= cnt) return;
        if (tid < BM) {
            int m = bm + tid;
            if (m < cnt) { stok[tid] = g_list[e * TT + m]; swt[tid] = g_wt[e * TT + m]; }
            else         { stok[tid] = -1; swt[tid] = 0.f; }
        }
        __syncthreads();
    }

    const float* Bbase = (MODE == 1) ? (Bm + (size_t)e * K * Nn) : Bm;
    unsigned a_smem = (unsigned)__cvta_generic_to_shared(As);
    unsigned b_smem = (unsigned)__cvta_generic_to_shared(Bs);

    // per-thread fill coords
    int aRow0 = tid >> 1;           // chunk pair: rows tid>>1 with segs (tid&1)*2, +1
    int aSeg0 = (tid & 1) * 2;

    auto fill_stage = [&](int s, int k0) {
        // A: 128 rows x 16 floats = 512 x 16B chunks (2/thread, consecutive segs)
        #pragma unroll
        for (int j = 0; j < 2; j++) {
            int row = aRow0, seg = aSeg0 + j;
            const float* src;
            int sz = 16;
            if (MODE == 1) {
                int tok = stok[row];
                if (tok >= 0) src = A + (size_t)tok * K + k0 + seg * 4;
                else { src = A; sz = 0; }
            } else {
                src = A + (size_t)(bm + row) * K + k0 + seg * 4;
            }
            unsigned dst = a_smem + (unsigned)((s * BM * AW + row * AW + seg * 4) * 4);
            cp16(dst, src, sz);
        }
        // B: 16 rows x 128 floats = 512 x 16B chunks (2/thread)
        #pragma unroll
        for (int j = 0; j < 2; j++) {
            int chunk = tid + j * 256;
            int krow = chunk >> 5, seg = chunk & 31;
            const float* src = Bbase + (size_t)(k0 + krow) * Nn + bn + seg * 4;
            unsigned dst = b_smem + (unsigned)((s * GBK * BWW + krow * BWW + seg * 4) * 4);
            cp16(dst, src, 16);
        }
    };

    // prologue: stages 0..GS-2
    #pragma unroll
    for (int s = 0; s < GS - 1; s++) {
        fill_stage(s, s * GBK);
        asm volatile("cp.async.commit_group;" ::: "memory");
    }

    int lane = tid & 31, wid = tid >> 5;
    int wm = (wid & 3) * 32;
    int wn = (wid >> 2) * 64;
    int g = lane >> 2, c = lane & 3;

    float acc[2][8][4];
    #pragma unroll
    for (int mi = 0; mi < 2; mi++)
        #pragma unroll
        for (int ni = 0; ni < 8; ni++)
            #pragma unroll
            for (int q = 0; q < 4; q++) acc[mi][ni][q] = 0.f;

    int nIter = K / GBK;
    for (int it = 0; it < nIter; it++) {
        asm volatile("cp.async.wait_group 2;" ::: "memory");
        __syncthreads();

        int nx = it + GS - 1;
        if (nx < nIter) fill_stage(nx & (GS - 1), nx * GBK);
        asm volatile("cp.async.commit_group;" ::: "memory");

        const float* Ab = As + (it & (GS - 1)) * BM * AW;
        const float* Bb = Bs + (it & (GS - 1)) * GBK * BWW;
        #pragma unroll
        for (int kk = 0; kk < GBK; kk += 8) {
            unsigned af[2][4];
            #pragma unroll
            for (int mi = 0; mi < 2; mi++) {
                int r0 = wm + mi * 16 + g;
                af[mi][0] = __float_as_uint(Ab[r0 * AW + kk + c]);
                af[mi][1] = __float_as_uint(Ab[(r0 + 8) * AW + kk + c]);
                af[mi][2] = __float_as_uint(Ab[r0 * AW + kk + c + 4]);
                af[mi][3] = __float_as_uint(Ab[(r0 + 8) * AW + kk + c + 4]);
            }
            #pragma unroll
            for (int ni = 0; ni < 8; ni++) {
                unsigned bf[2];
                bf[0] = __float_as_uint(Bb[(kk + c) * BWW + wn + ni * 8 + g]);
                bf[1] = __float_as_uint(Bb[(kk + c + 4) * BWW + wn + ni * 8 + g]);
                mma8(acc[0][ni], af[0], bf);
                mma8(acc[1][ni], af[1], bf);
            }
        }
    }

    // epilogue
    #pragma unroll
    for (int mi = 0; mi < 2; mi++) {
        int rl0 = wm + mi * 16 + g;
        int rl1 = rl0 + 8;
        if (MODE == 1) {
            int tk0 = stok[rl0], tk1 = stok[rl1];
            float w0 = swt[rl0], w1 = swt[rl1];
            #pragma unroll
            for (int ni = 0; ni < 8; ni++) {
                int cn = bn + wn + ni * 8 + 2 * c;
                float b0 = bias[(size_t)e * Nn + cn], b1 = bias[(size_t)e * Nn + cn + 1];
                if (tk0 >= 0) {
                    float* p = Cm + (size_t)tk0 * Nn + cn;
                    atomicAdd(p,     w0 * (acc[mi][ni][0] + b0));
                    atomicAdd(p + 1, w0 * (acc[mi][ni][1] + b1));
                }
                if (tk1 >= 0) {
                    float* p = Cm + (size_t)tk1 * Nn + cn;
                    atomicAdd(p,     w1 * (acc[mi][ni][2] + b0));
                    atomicAdd(p + 1, w1 * (acc[mi][ni][3] + b1));
                }
            }
        } else if (MODE == 2) {
            int r0 = bm + rl0, r1 = bm + rl1;
            int b0r = r0 >> 10, n0 = r0 & 1023;
            int b1r = r1 >> 10, n1 = r1 & 1023;
            #pragma unroll
            for (int ni = 0; ni < 8; ni++) {
                int cn = bn + wn + ni * 8 + 2 * c;
                int sect = cn / CC;          // 0=Q 1=K 2=V (uniform per block)
                int cc = cn - sect * CC;
                int h = cc >> 6, d = cc & 63;
                if (sect == 0) {
                    size_t i0 = ((size_t)(b0r * HH + h) * NN + n0) * DH + d;
                    size_t i1 = ((size_t)(b1r * HH + h) * NN + n1) * DH + d;
                    *(unsigned*)&qb[i0] = f2bf2(acc[mi][ni][0] * 0.125f, acc[mi][ni][1] * 0.125f);
                    *(unsigned*)&qb[i1] = f2bf2(acc[mi][ni][2] * 0.125f, acc[mi][ni][3] * 0.125f);
                } else if (sect == 1) {
                    size_t i0 = ((size_t)(b0r * HH + h) * NN + n0) * DH + d;
                    size_t i1 = ((size_t)(b1r * HH + h) * NN + n1) * DH + d;
                    *(unsigned*)&kb[i0] = f2bf2(acc[mi][ni][0], acc[mi][ni][1]);
                    *(unsigned*)&kb[i1] = f2bf2(acc[mi][ni][2], acc[mi][ni][3]);
                } else {
                    size_t base0 = (size_t)(b0r * HH + h) * DH;
                    size_t base1 = (size_t)(b1r * HH + h) * DH;
                    vtb[(base0 + d) * NN + n0]     = __float2bfloat16_rn(acc[mi][ni][0]);
                    vtb[(base0 + d + 1) * NN + n0] = __float2bfloat16_rn(acc[mi][ni][1]);
                    vtb[(base1 + d) * NN + n1]     = __float2bfloat16_rn(acc[mi][ni][2]);
                    vtb[(base1 + d + 1) * NN + n1] = __float2bfloat16_rn(acc[mi][ni][3]);
                }
            }
        } else {
            int r0 = bm + rl0, r1 = bm + rl1;
            #pragma unroll
            for (int ni = 0; ni < 8; ni++) {
                int cn = bn + wn + ni * 8 + 2 * c;
                float2 v0 = make_float2(acc[mi][ni][0], acc[mi][ni][1]);
                float2 v1 = make_float2(acc[mi][ni][2], acc[mi][ni][3]);
                if (bias) {
                    float b0 = bias[cn], b1 = bias[cn + 1];
                    v0.x += b0; v0.y += b1; v1.x += b0; v1.y += b1;
                }
                if (resid) {
                    float2 r0v = *(const float2*)(resid + (size_t)r0 * Nn + cn);
                    float2 r1v = *(const float2*)(resid + (size_t)r1 * Nn + cn);
                    v0.x += r0v.x; v0.y += r0v.y; v1.x += r1v.x; v1.y += r1v.y;
                }
                *(float2*)(Cm + (size_t)r0 * Nn + cn) = v0;
                *(float2*)(Cm + (size_t)r1 * Nn + cn) = v1;
            }
        }
    }
}

// ---------------- bf16 flash attention, contiguous operands ----------------
#define QSTRW 36
#define KSTRW 36
#define ATTN_SMEM ((128*QSTRW + 2*64*KSTRW + 2*64*KSTRW) * 4)

__global__ __launch_bounds__(256, 2) void attn_bf16_kernel(
    const __nv_bfloat16* __restrict__ qb,
    const __nv_bfloat16* __restrict__ kb,
    const __nv_bfloat16* __restrict__ vt,
    float* __restrict__ o)
{
    extern __shared__ unsigned smem_u[];
    unsigned* QPs = smem_u;
    unsigned* Ks  = QPs + 128 * QSTRW;
    unsigned* Vs  = Ks + 2 * 64 * KSTRW;

    int bh = blockIdx.y;
    int bb = bh / HH, hh = bh % HH;
    int q0 = blockIdx.x * 128;
    int tid = threadIdx.x;
    int lane = tid & 31, wid = tid >> 5;
    int wm = wid * 16;
    int g = lane >> 2, c = lane & 3;

    const __nv_bfloat16* q_head = qb + ((size_t)(bb * HH + hh) * NN + q0) * DH;
    const __nv_bfloat16* k_head = kb + (size_t)(bb * HH + hh) * NN * DH;
    const __nv_bfloat16* v_head = vt + (size_t)(bb * HH + hh) * DH * NN;

    {
        int row = tid >> 1, seg = tid & 1;
        const uint4* src = (const uint4*)(q_head + (size_t)row * DH + seg * 32);
        unsigned* dst = QPs + row * QSTRW + seg * 16;
        #pragma unroll
        for (int i = 0; i < 4; i++)
            *(uint4*)(dst + i * 4) = src[i];
    }
    __syncthreads();

    unsigned qf[4][4];
    #pragma unroll
    for (int kc = 0; kc < 4; kc++) {
        int bw = kc * 8 + c;
        qf[kc][0] = QPs[(wm + g) * QSTRW + bw];
        qf[kc][1] = QPs[(wm + g + 8) * QSTRW + bw];
        qf[kc][2] = QPs[(wm + g) * QSTRW + bw + 4];
        qf[kc][3] = QPs[(wm + g + 8) * QSTRW + bw + 4];
    }
    __syncthreads();

    float oacc[8][4];
    #pragma unroll
    for (int ni = 0; ni < 8; ni++)
        #pragma unroll
        for (int q = 0; q < 4; q++) oacc[ni][q] = 0.f;
    float m0 = -1e30f, m1 = -1e30f, l0 = 0.f, l1 = 0.f;

    int ktok = tid & 63, kseg = tid >> 6;
    int vd = tid & 63, vseg = tid >> 6;

    {
        const uint4* ksrc = (const uint4*)(k_head + (size_t)ktok * DH);
        *(uint4*)(Ks + ktok * KSTRW + kseg * 4) = ksrc[kseg];
        *(uint4*)(Ks + ktok * KSTRW + (kseg + 4) * 4) = ksrc[kseg + 4];
        const __nv_bfloat16* vrow = v_head + (size_t)vd * NN;
        *(uint4*)(Vs + vd * KSTRW + vseg * 4)       = *(const uint4*)(vrow + vseg * 8);
        *(uint4*)(Vs + vd * KSTRW + (vseg + 4) * 4) = *(const uint4*)(vrow + (vseg + 4) * 8);
    }
    __syncthreads();

    const int NTILES = NN / 64;
    for (int tile = 0; tile < NTILES; tile++) {
        int cur = tile & 1, nxt = cur ^ 1;
        const unsigned* Kb = Ks + cur * 64 * KSTRW;
        const unsigned* Vb = Vs + cur * 64 * KSTRW;
        bool more = (tile + 1 < NTILES);

        uint4 kx0, kx1, vx0, vx1;
        if (more) {
            const uint4* ksrc = (const uint4*)(k_head + (size_t)(tile + 1) * 64 * DH + (size_t)ktok * DH);
            kx0 = ksrc[kseg]; kx1 = ksrc[kseg + 4];
            const __nv_bfloat16* vrow = v_head + (size_t)vd * NN + (tile + 1) * 64;
            vx0 = *(const uint4*)(vrow + vseg * 8);
            vx1 = *(const uint4*)(vrow + (vseg + 4) * 8);
        }

        float sa[8][4];
        #pragma unroll
        for (int ni = 0; ni < 8; ni++)
            #pragma unroll
            for (int q = 0; q < 4; q++) sa[ni][q] = 0.f;
        #pragma unroll
        for (int kc = 0; kc < 4; kc++) {
            #pragma unroll
            for (int ni = 0; ni < 8; ni++) {
                int bw = (ni * 8 + g) * KSTRW + kc * 8 + c;
                mma16(sa[ni], qf[kc], Kb[bw], Kb[bw + 4]);
            }
        }

        float mx0 = -1e30f, mx1 = -1e30f;
        #pragma unroll
        for (int ni = 0; ni < 8; ni++) {
            mx0 = fmaxf(mx0, fmaxf(sa[ni][0], sa[ni][1]));
            mx1 = fmaxf(mx1, fmaxf(sa[ni][2], sa[ni][3]));
        }
        mx0 = fmaxf(mx0, __shfl_xor_sync(~0u, mx0, 1));
        mx0 = fmaxf(mx0, __shfl_xor_sync(~0u, mx0, 2));
        mx1 = fmaxf(mx1, __shfl_xor_sync(~0u, mx1, 1));
        mx1 = fmaxf(mx1, __shfl_xor_sync(~0u, mx1, 2));
        float mn0 = fmaxf(m0, mx0), mn1 = fmaxf(m1, mx1);
        float al0 = __expf(m0 - mn0), al1 = __expf(m1 - mn1);
        float sum0 = 0.f, sum1 = 0.f;
        #pragma unroll
        for (int ni = 0; ni < 8; ni++) {
            float p00 = __expf(sa[ni][0] - mn0);
            float p01 = __expf(sa[ni][1] - mn0);
            float p10 = __expf(sa[ni][2] - mn1);
            float p11 = __expf(sa[ni][3] - mn1);
            sum0 += p00 + p01; sum1 += p10 + p11;
            QPs[(wm + g) * QSTRW + ni * 4 + c]     = f2bf2(p00, p01);
            QPs[(wm + g + 8) * QSTRW + ni * 4 + c] = f2bf2(p10, p11);
        }
        sum0 += __shfl_xor_sync(~0u, sum0, 1);
        sum0 += __shfl_xor_sync(~0u, sum0, 2);
        sum1 += __shfl_xor_sync(~0u, sum1, 1);
        sum1 += __shfl_xor_sync(~0u, sum1, 2);
        l0 = l0 * al0 + sum0; l1 = l1 * al1 + sum1;
        m0 = mn0; m1 = mn1;
        #pragma unroll
        for (int ni = 0; ni < 8; ni++) {
            oacc[ni][0] *= al0; oacc[ni][1] *= al0;
            oacc[ni][2] *= al1; oacc[ni][3] *= al1;
        }
        __syncwarp();

        if (more) {
            unsigned* Kn = Ks + nxt * 64 * KSTRW;
            *(uint4*)(Kn + ktok * KSTRW + kseg * 4) = kx0;
            *(uint4*)(Kn + ktok * KSTRW + (kseg + 4) * 4) = kx1;
        }

        #pragma unroll
        for (int kc = 0; kc < 4; kc++) {
            unsigned af[4];
            int bw = kc * 8 + c;
            af[0] = QPs[(wm + g) * QSTRW + bw];
            af[1] = QPs[(wm + g + 8) * QSTRW + bw];
            af[2] = QPs[(wm + g) * QSTRW + bw + 4];
            af[3] = QPs[(wm + g + 8) * QSTRW + bw + 4];
            #pragma unroll
            for (int ni = 0; ni < 8; ni++) {
                int vw = (ni * 8 + g) * KSTRW + kc * 8 + c;
                mma16(oacc[ni], af, Vb[vw], Vb[vw + 4]);
            }
        }

        if (more) {
            unsigned* Vn = Vs + nxt * 64 * KSTRW;
            *(uint4*)(Vn + vd * KSTRW + vseg * 4) = vx0;
            *(uint4*)(Vn + vd * KSTRW + (vseg + 4) * 4) = vx1;
        }
        __syncthreads();
    }

    float inv0 = 1.f / l0, inv1 = 1.f / l1;
    size_t t0 = (size_t)bb * NN + q0 + wm + g;
    size_t t1 = t0 + 8;
    #pragma unroll
    for (int ni = 0; ni < 8; ni++) {
        int d = hh * DH + ni * 8 + 2 * c;
        *(float2*)&o[t0 * CC + d] = make_float2(tfround(oacc[ni][0] * inv0), tfround(oacc[ni][1] * inv0));
        *(float2*)&o[t1 * CC + d] = make_float2(tfround(oacc[ni][2] * inv1), tfround(oacc[ni][3] * inv1));
    }
}

// ---------------- router ----------------
__global__ __launch_bounds__(256) void route_kernel(
    const float* __restrict__ h2, const float* __restrict__ route_w,
    const float* __restrict__ route_b, const float* __restrict__ rln_g,
    const float* __restrict__ rln_b, const float* __restrict__ noise)
{
    int warp = threadIdx.x >> 5, lane = threadIdx.x & 31;
    int t = blockIdx.x * 8 + warp;
    const float* hrow = h2 + (size_t)t * CC;
    float acc[EE];
    #pragma unroll
    for (int e = 0; e < EE; e++) acc[e] = 0.f;
    for (int c = lane; c < CC; c += 32) {
        float hv = hrow[c];
        const float* rw = route_w + (size_t)c * EE;
        #pragma unroll
        for (int e = 0; e < EE; e++) acc[e] += hv * rw[e];
    }
    #pragma unroll
    for (int e = 0; e < EE; e++)
        #pragma unroll
        for (int off = 16; off > 0; off >>= 1)
            acc[e] += __shfl_xor_sync(~0u, acc[e], off);

    if (lane == 0) {
        float lg[EE];
        float mean = 0.f;
        #pragma unroll
        for (int e = 0; e < EE; e++) { lg[e] = acc[e] + route_b[e]; mean += lg[e]; }
        mean *= (1.f / EE);
        float var = 0.f;
        #pragma unroll
        for (int e = 0; e < EE; e++) { float d = lg[e] - mean; var += d * d; }
        var *= (1.f / EE);
        float rstd = rsqrtf(var + 1e-5f);
        float mx = -1e30f;
        #pragma unroll
        for (int e = 0; e < EE; e++) { lg[e] = (lg[e] - mean) * rstd * rln_g[e] + rln_b[e]; mx = fmaxf(mx, lg[e]); }
        float den = 0.f;
        float r[EE];
        #pragma unroll
        for (int e = 0; e < EE; e++) { r[e] = __expf(lg[e] - mx); den += r[e]; }
        float inv = 1.f / den;
        const float* nrow = noise + (size_t)t * EE;
        #pragma unroll
        for (int e = 0; e < EE; e++) r[e] = r[e] * inv + nrow[e] * 0.125f;

        int i1 = 0;
        #pragma unroll
        for (int e = 1; e < EE; e++) if (r[e] > r[i1]) i1 = e;
        int i2 = (i1 == 0) ? 1 : 0;
        #pragma unroll
        for (int e = 0; e < EE; e++) if (e != i1 && r[e] > r[i2]) i2 = e;

        float vm = fmaxf(r[i1], r[i2]);
        float e1 = __expf(r[i1] - vm), e2 = __expf(r[i2] - vm);
        float wsum = 1.f / (e1 + e2);
        float w1 = e1 * wsum, w2 = e2 * wsum;

        int p1 = atomicAdd(&g_cnt[i1], 1);
        g_list[i1 * TT + p1] = t; g_wt[i1 * TT + p1] = w1;
        int p2 = atomicAdd(&g_cnt[i2], 1);
        g_list[i2 * TT + p2] = t; g_wt[i2 * TT + p2] = w2;
    }
}

__global__ void zero_cnt_kernel() { if (threadIdx.x < EE) g_cnt[threadIdx.x] = 0; }

// ---------------- launch ----------------
extern "C" void kernel_launch(void* const* d_in, const int* in_sizes, int n_in,
                              void* d_out, int out_size)
{
    const float* x       = (const float*)d_in[0];
    const float* noise   = (const float*)d_in[1];
    const float* ln1_g   = (const float*)d_in[2];
    const float* ln1_b   = (const float*)d_in[3];
    const float* qkv_w   = (const float*)d_in[4];
    const float* proj_w  = (const float*)d_in[5];
    const float* proj_b  = (const float*)d_in[6];
    const float* ln2_g   = (const float*)d_in[7];
    const float* ln2_b   = (const float*)d_in[8];
    const float* route_w = (const float*)d_in[9];
    const float* route_b = (const float*)d_in[10];
    const float* rln_g   = (const float*)d_in[11];
    const float* rln_b   = (const float*)d_in[12];
    const float* exp_w   = (const float*)d_in[13];
    const float* exp_b   = (const float*)d_in[14];
    float* out = (float*)d_out;

    float *h1, *o, *h2, *h2r, *qkvwr, *projwr, *expwr;
    __nv_bfloat16 *qbp, *kbp, *vtp;
    cudaGetSymbolAddress((void**)&h1,  g_h1);
    cudaGetSymbolAddress((void**)&o,   g_o);
    cudaGetSymbolAddress((void**)&h2,  g_h2);
    cudaGetSymbolAddress((void**)&h2r, g_h2r);
    cudaGetSymbolAddress((void**)&qkvwr,  g_qkvwr);
    cudaGetSymbolAddress((void**)&projwr, g_projwr);
    cudaGetSymbolAddress((void**)&expwr,  g_expwr);
    cudaGetSymbolAddress((void**)&qbp, g_qb);
    cudaGetSymbolAddress((void**)&kbp, g_kb);
    cudaGetSymbolAddress((void**)&vtp, g_vt);

    cudaFuncSetAttribute(attn_bf16_kernel, cudaFuncAttributeMaxDynamicSharedMemorySize, (int)ATTN_SMEM);
    cudaFuncSetAttribute(tf32_gemm_kernel<0>, cudaFuncAttributeMaxDynamicSharedMemorySize, (int)GEMM_SMEM);
    cudaFuncSetAttribute(tf32_gemm_kernel<1>, cudaFuncAttributeMaxDynamicSharedMemorySize, (int)GEMM_SMEM);
    cudaFuncSetAttribute(tf32_gemm_kernel<2>, cudaFuncAttributeMaxDynamicSharedMemorySize, (int)GEMM_SMEM);

    // 0) pre-round weights to tf32
    round_kernel<<<(CC * 3 * CC) / 256, 256>>>(qkv_w, qkvwr, CC * 3 * CC);
    round_kernel<<<(CC * CC) / 256, 256>>>(proj_w, projwr, CC * CC);
    round_kernel<<<(EE * CC * CC) / 256, 256>>>(exp_w, expwr, EE * CC * CC);
    // 1) LN1 -> rounded h1
    ln_kernel<<<TT, 256>>>(x, ln1_g, ln1_b, nullptr, h1);
    // 2) QKV GEMM -> bf16 q/k/vt
    tf32_gemm_kernel<2><<<dim3(3 * CC / BN, TT / BM), 256, GEMM_SMEM>>>(
        h1, qkvwr, nullptr, 3 * CC, CC, nullptr, nullptr, qbp, kbp, vtp);
    // 3) attention -> rounded o
    attn_bf16_kernel<<<dim3(NN / 128, BB * HH), 256, ATTN_SMEM>>>(qbp, kbp, vtp, o);
    // 4) proj + bias + residual -> d_out
    tf32_gemm_kernel<0><<<dim3(CC / BN, TT / BM), 256, GEMM_SMEM>>>(
        o, projwr, out, CC, CC, proj_b, x, nullptr, nullptr, nullptr);
    // 5) LN2 -> full h2 (router) + rounded h2r (MoE)
    ln_kernel<<<TT, 256>>>(out, ln2_g, ln2_b, h2, h2r);
    // 6) routing
    zero_cnt_kernel<<<1, 32>>>();
    route_kernel<<<TT / 8, 256>>>(h2, route_w, route_b, rln_g, rln_b, noise);
    // 7) MoE grouped GEMM, accumulates into d_out
    tf32_gemm_kernel<1><<<dim3(CC / BN, TT / BM, EE), 256, GEMM_SMEM>>>(
        h2r, expwr, out, CC, CC, exp_b, nullptr, nullptr, nullptr, nullptr);
}